// round 2
// baseline (speedup 1.0000x reference)
#include <cuda_runtime.h>
#include <math.h>

// Problem constants
#define Bn 4
#define Rn 512
#define Cn 512
#define En 256
#define Hn 16
#define Dn 16
#define Mn 16
#define Fn 512

// ---------------- scratch (device globals; no allocation) ----------------
__device__ float g_q[Bn*Rn*En];     // Q   [B*R, H*D]
__device__ float g_k[Bn*Cn*En];     // K
__device__ float g_v[Bn*Cn*En];     // V
__device__ float g_att[Bn*Rn*En];   // attention out_concat
__device__ float g_y[Bn*Rn*En];     // row_emb + mh
__device__ float g_x[Bn*Rn*En];     // after norm1
__device__ float g_h[Bn*Rn*Fn];     // ffn hidden
__device__ float g_z[Bn*Rn*En];     // x + ffn

// ---------------- generic register-blocked SGEMM ----------------
// C[M,N] = A[M,K] @ B[K,N] (+bias[n]) (+res[m,n]) (optional relu)
// BM=BN=64, BK=16, 256 threads, 4x4 micro-tile. M%64==0, N%64==0, K%16==0.
template<bool RELU, bool RES>
__global__ __launch_bounds__(256)
void gemm64(const float* __restrict__ A, const float* __restrict__ B,
            const float* __restrict__ bias, const float* __restrict__ res,
            float* __restrict__ C, int M, int N, int K)
{
    __shared__ float As[16][64];
    __shared__ float Bs[16][64];
    const int tid = threadIdx.x;
    const int tx = tid & 15;        // 0..15  -> n micro
    const int ty = tid >> 4;        // 0..15  -> m micro
    const int m0 = blockIdx.y * 64;
    const int n0 = blockIdx.x * 64;

    const int arow = tid >> 2;          // 0..63
    const int acol = (tid & 3) * 4;     // 0,4,8,12
    const int brow = tid >> 4;          // 0..15
    const int bcol = (tid & 15) * 4;    // 0..60

    float acc[4][4] = {};

    for (int k0 = 0; k0 < K; k0 += 16) {
        float4 av = *reinterpret_cast<const float4*>(&A[(size_t)(m0 + arow) * K + k0 + acol]);
        float4 bv = *reinterpret_cast<const float4*>(&B[(size_t)(k0 + brow) * N + n0 + bcol]);
        __syncthreads();
        As[acol + 0][arow] = av.x;
        As[acol + 1][arow] = av.y;
        As[acol + 2][arow] = av.z;
        As[acol + 3][arow] = av.w;
        *reinterpret_cast<float4*>(&Bs[brow][bcol]) = bv;
        __syncthreads();
#pragma unroll
        for (int k = 0; k < 16; k++) {
            float a[4], b[4];
#pragma unroll
            for (int i = 0; i < 4; i++) a[i] = As[k][ty * 4 + i];
#pragma unroll
            for (int j = 0; j < 4; j++) b[j] = Bs[k][tx * 4 + j];
#pragma unroll
            for (int i = 0; i < 4; i++)
#pragma unroll
                for (int j = 0; j < 4; j++)
                    acc[i][j] = fmaf(a[i], b[j], acc[i][j]);
        }
    }

#pragma unroll
    for (int i = 0; i < 4; i++) {
        int m = m0 + ty * 4 + i;
#pragma unroll
        for (int j = 0; j < 4; j++) {
            int n = n0 + tx * 4 + j;
            float v = acc[i][j];
            if (bias) v += bias[n];
            if (RES)  v += res[(size_t)m * N + n];
            if (RELU) v = fmaxf(v, 0.0f);
            C[(size_t)m * N + n] = v;
        }
    }
}

// ---------------- fused attention: dot + mix-MLP + softmax + PV ----------------
// grid: (B*H, R/64), block: 256 threads (8 warps), one warp per row.
// Dynamic shared: K tile (512 x 16, stride 17), V tile (stride 17), Q chunk (64x16).
#define KV_STRIDE 17
#define ATTN_SMEM ((Cn * KV_STRIDE * 2 + 64 * Dn) * (int)sizeof(float))

__global__ __launch_bounds__(256)
void attn_kernel(const float* __restrict__ Q, const float* __restrict__ K,
                 const float* __restrict__ V, const float* __restrict__ cost,
                 const float* __restrict__ mix1_w, const float* __restrict__ mix1_b,
                 const float* __restrict__ mix2_w, const float* __restrict__ mix2_b,
                 float* __restrict__ Out)
{
    extern __shared__ float sh[];
    float* ksh = sh;                      // Cn * 17
    float* vsh = sh + Cn * KV_STRIDE;     // Cn * 17
    float* qsh = vsh + Cn * KV_STRIDE;    // 64 * 16

    __shared__ float swd[Mn], swc[Mn], swb[Mn], sw2[Mn];
    __shared__ float sb2;

    const int tid = threadIdx.x;
    const int b = blockIdx.x / Hn;
    const int h = blockIdx.x % Hn;
    const int r0 = blockIdx.y * 64;

    // mix MLP params for this head
    if (tid < Mn) {
        swd[tid] = mix1_w[h * 2 * Mn + tid];        // weight on dot
        swc[tid] = mix1_w[h * 2 * Mn + Mn + tid];   // weight on cost
        swb[tid] = mix1_b[h * Mn + tid];
        sw2[tid] = mix2_w[h * Mn + tid];
    }
    if (tid == 0) sb2 = mix2_b[h];

    // load K, V (all 512 cols, this head) into shared
    for (int idx = tid; idx < Cn * Dn; idx += 256) {
        int c = idx >> 4, d = idx & 15;
        ksh[c * KV_STRIDE + d] = K[((size_t)(b * Cn + c)) * En + h * Dn + d];
        vsh[c * KV_STRIDE + d] = V[((size_t)(b * Cn + c)) * En + h * Dn + d];
    }
    // load Q chunk
    for (int idx = tid; idx < 64 * Dn; idx += 256) {
        int rr = idx >> 4, d = idx & 15;
        qsh[idx] = Q[((size_t)(b * Rn + r0 + rr)) * En + h * Dn + d];
    }
    __syncthreads();

    const int warp = tid >> 5;
    const int lane = tid & 31;
    const float sb2r = sb2;

    for (int rr = warp; rr < 64; rr += 8) {
        const int r = r0 + rr;
        const float* qrow = &qsh[rr * Dn];
        const float* crow = &cost[((size_t)(b * Rn + r)) * Cn];

        float dotv[16], cv[16], mixed[16];
        // --- scores: dot product + cost ---
#pragma unroll
        for (int i = 0; i < 16; i++) {
            int c = lane + 32 * i;
            const float* kc = &ksh[c * KV_STRIDE];
            float acc = 0.0f;
#pragma unroll
            for (int d = 0; d < Dn; d++) acc = fmaf(qrow[d], kc[d], acc);
            dotv[i] = acc * 0.25f;          // 1/sqrt(16)
            cv[i]   = crow[c];
            mixed[i] = sb2r;
        }
        // --- mix MLP: 2 -> 16 relu -> 1 (m-outer so weights stay in regs) ---
#pragma unroll
        for (int m = 0; m < Mn; m++) {
            float wd = swd[m], wc = swc[m], wb = swb[m], w2 = sw2[m];
#pragma unroll
            for (int i = 0; i < 16; i++) {
                float t = fmaf(dotv[i], wd, fmaf(cv[i], wc, wb));
                mixed[i] = fmaf(fmaxf(t, 0.0f), w2, mixed[i]);
            }
        }
        // --- softmax over c (warp-wide: 16 per lane x 32 lanes = 512) ---
        float lmax = -1e30f;
#pragma unroll
        for (int i = 0; i < 16; i++) lmax = fmaxf(lmax, mixed[i]);
#pragma unroll
        for (int off = 16; off; off >>= 1)
            lmax = fmaxf(lmax, __shfl_xor_sync(0xFFFFFFFFu, lmax, off));
        float lsum = 0.0f;
#pragma unroll
        for (int i = 0; i < 16; i++) {
            float e = __expf(mixed[i] - lmax);
            mixed[i] = e;
            lsum += e;
        }
#pragma unroll
        for (int off = 16; off; off >>= 1)
            lsum += __shfl_xor_sync(0xFFFFFFFFu, lsum, off);
        const float inv = 1.0f / lsum;

        // --- PV: out[d] = sum_c p_c * v[c][d] ---
        float o[16];
#pragma unroll
        for (int d = 0; d < 16; d++) o[d] = 0.0f;
#pragma unroll
        for (int i = 0; i < 16; i++) {
            int c = lane + 32 * i;
            float p = mixed[i];
            const float* vc = &vsh[c * KV_STRIDE];
#pragma unroll
            for (int d = 0; d < 16; d++) o[d] = fmaf(p, vc[d], o[d]);
        }
#pragma unroll
        for (int d = 0; d < 16; d++) {
#pragma unroll
            for (int off = 16; off; off >>= 1)
                o[d] += __shfl_xor_sync(0xFFFFFFFFu, o[d], off);
        }
        if (lane < 16)
            Out[((size_t)(b * Rn + r)) * En + h * Dn + lane] = o[lane] * inv;
    }
}

// ---------------- instance norm over R per (b, e) ----------------
// grid: (E/64, B), block: (64, 4)
__global__ __launch_bounds__(256)
void inorm_kernel(const float* __restrict__ X, const float* __restrict__ gamma,
                  const float* __restrict__ beta, float* __restrict__ Y)
{
    const int b = blockIdx.y;
    const int e = blockIdx.x * 64 + threadIdx.x;
    const int ty = threadIdx.y;
    const float* xb = X + (size_t)b * Rn * En;
    float* yb = Y + (size_t)b * Rn * En;

    float s = 0.0f, s2 = 0.0f;
    for (int r = ty; r < Rn; r += 4) {
        float v = xb[(size_t)r * En + e];
        s += v; s2 += v * v;
    }
    __shared__ float ss[4][64], sq[4][64];
    __shared__ float sa[64], sb[64];
    ss[ty][threadIdx.x] = s;
    sq[ty][threadIdx.x] = s2;
    __syncthreads();
    if (ty == 0) {
        float t  = ss[0][threadIdx.x] + ss[1][threadIdx.x] + ss[2][threadIdx.x] + ss[3][threadIdx.x];
        float t2 = sq[0][threadIdx.x] + sq[1][threadIdx.x] + sq[2][threadIdx.x] + sq[3][threadIdx.x];
        float mean = t * (1.0f / Rn);
        float var  = t2 * (1.0f / Rn) - mean * mean;
        float rstd = rsqrtf(var + 1e-5f);
        float a = gamma[e] * rstd;
        sa[threadIdx.x] = a;
        sb[threadIdx.x] = beta[e] - mean * a;
    }
    __syncthreads();
    const float a = sa[threadIdx.x], bb = sb[threadIdx.x];
    for (int r = ty; r < Rn; r += 4)
        yb[(size_t)r * En + e] = fmaf(xb[(size_t)r * En + e], a, bb);
}

// ---------------- launch ----------------
extern "C" void kernel_launch(void* const* d_in, const int* in_sizes, int n_in,
                              void* d_out, int out_size)
{
    const float* row_emb = (const float*)d_in[0];
    const float* col_emb = (const float*)d_in[1];
    const float* cost    = (const float*)d_in[2];
    const float* Wq      = (const float*)d_in[3];
    const float* Wk      = (const float*)d_in[4];
    const float* Wv      = (const float*)d_in[5];
    const float* mix1_w  = (const float*)d_in[6];
    const float* mix1_b  = (const float*)d_in[7];
    const float* mix2_w  = (const float*)d_in[8];
    const float* mix2_b  = (const float*)d_in[9];
    const float* Wc      = (const float*)d_in[10];
    const float* bc      = (const float*)d_in[11];
    const float* W1      = (const float*)d_in[12];
    const float* b1      = (const float*)d_in[13];
    const float* W2      = (const float*)d_in[14];
    const float* b2      = (const float*)d_in[15];
    const float* g1      = (const float*)d_in[16];
    const float* be1     = (const float*)d_in[17];
    const float* g2      = (const float*)d_in[18];
    const float* be2     = (const float*)d_in[19];
    float* out = (float*)d_out;

    float *q, *k, *v, *att, *y, *x, *hh, *z;
    cudaGetSymbolAddress((void**)&q,   g_q);
    cudaGetSymbolAddress((void**)&k,   g_k);
    cudaGetSymbolAddress((void**)&v,   g_v);
    cudaGetSymbolAddress((void**)&att, g_att);
    cudaGetSymbolAddress((void**)&y,   g_y);
    cudaGetSymbolAddress((void**)&x,   g_x);
    cudaGetSymbolAddress((void**)&hh,  g_h);
    cudaGetSymbolAddress((void**)&z,   g_z);

    cudaFuncSetAttribute(attn_kernel, cudaFuncAttributeMaxDynamicSharedMemorySize, ATTN_SMEM);

    const int MR = Bn * Rn;   // 2048

    // QKV projections
    {
        dim3 g(En / 64, MR / 64);
        gemm64<false, false><<<g, 256>>>(row_emb, Wq, nullptr, nullptr, q, MR, En, En);
        gemm64<false, false><<<g, 256>>>(col_emb, Wk, nullptr, nullptr, k, MR, En, En);
        gemm64<false, false><<<g, 256>>>(col_emb, Wv, nullptr, nullptr, v, MR, En, En);
    }

    // fused attention (scores + mix MLP + softmax + PV)
    {
        dim3 g(Bn * Hn, Rn / 64);
        attn_kernel<<<g, 256, ATTN_SMEM>>>(q, k, v, cost, mix1_w, mix1_b, mix2_w, mix2_b, att);
    }

    // multi_head_combine + residual: y = row_emb + att @ Wc + bc
    {
        dim3 g(En / 64, MR / 64);
        gemm64<false, true><<<g, 256>>>(att, Wc, bc, row_emb, y, MR, En, En);
    }

    // instance norm 1: x = IN(y)
    {
        dim3 g(En / 64, Bn);
        inorm_kernel<<<g, dim3(64, 4)>>>(y, g1, be1, x);
    }

    // FFN
    {
        dim3 g1d(Fn / 64, MR / 64);
        gemm64<true, false><<<g1d, 256>>>(x, W1, b1, nullptr, hh, MR, Fn, En);
        dim3 g2d(En / 64, MR / 64);
        gemm64<false, true><<<g2d, 256>>>(hh, W2, b2, x, z, MR, En, Fn);
    }

    // instance norm 2 -> output
    {
        dim3 g(En / 64, Bn);
        inorm_kernel<<<g, dim3(64, 4)>>>(z, g2, be2, out);
    }
}

// round 3
// speedup vs baseline: 1.9510x; 1.9510x over previous
#include <cuda_runtime.h>
#include <math.h>

#define Bn 4
#define Rn 512
#define Cn 512
#define En 256
#define Hn 16
#define Dn 16
#define Mn 16
#define Fn 512

// ---------------- scratch ----------------
__device__ float g_q[Bn*Rn*En];
__device__ float g_k[Bn*Cn*En];
__device__ float g_v[Bn*Cn*En];
__device__ float g_att[Bn*Rn*En];
__device__ float g_y[Bn*Rn*En];
__device__ float g_x[Bn*Rn*En];
__device__ float g_h[Bn*Rn*Fn];
__device__ float g_z[Bn*Rn*En];

// ---------------- SGEMM body (BM=BN=64, BK=16, 256 thr, 4x4 micro) ----------------
template<bool RELU, bool RES>
__device__ __forceinline__
void gemm_body(const float* __restrict__ A, const float* __restrict__ B,
               const float* __restrict__ bias, const float* __restrict__ res,
               float* __restrict__ C, int M, int N, int K)
{
    __shared__ float As[16][64];
    __shared__ float Bs[16][64];
    const int tid = threadIdx.x;
    const int tx = tid & 15;
    const int ty = tid >> 4;
    const int m0 = blockIdx.y * 64;
    const int n0 = blockIdx.x * 64;

    const int arow = tid >> 2;
    const int acol = (tid & 3) * 4;
    const int brow = tid >> 4;
    const int bcol = (tid & 15) * 4;

    float acc[4][4] = {};

    for (int k0 = 0; k0 < K; k0 += 16) {
        float4 av = *reinterpret_cast<const float4*>(&A[(size_t)(m0 + arow) * K + k0 + acol]);
        float4 bv = *reinterpret_cast<const float4*>(&B[(size_t)(k0 + brow) * N + n0 + bcol]);
        __syncthreads();
        As[acol + 0][arow] = av.x;
        As[acol + 1][arow] = av.y;
        As[acol + 2][arow] = av.z;
        As[acol + 3][arow] = av.w;
        *reinterpret_cast<float4*>(&Bs[brow][bcol]) = bv;
        __syncthreads();
#pragma unroll
        for (int k = 0; k < 16; k++) {
            float a[4], b[4];
#pragma unroll
            for (int i = 0; i < 4; i++) a[i] = As[k][ty * 4 + i];
#pragma unroll
            for (int j = 0; j < 4; j++) b[j] = Bs[k][tx * 4 + j];
#pragma unroll
            for (int i = 0; i < 4; i++)
#pragma unroll
                for (int j = 0; j < 4; j++)
                    acc[i][j] = fmaf(a[i], b[j], acc[i][j]);
        }
    }

#pragma unroll
    for (int i = 0; i < 4; i++) {
        int m = m0 + ty * 4 + i;
#pragma unroll
        for (int j = 0; j < 4; j++) {
            int n = n0 + tx * 4 + j;
            float v = acc[i][j];
            if (bias) v += bias[n];
            if (RES)  v += res[(size_t)m * N + n];
            if (RELU) v = fmaxf(v, 0.0f);
            C[(size_t)m * N + n] = v;
        }
    }
}

template<bool RELU, bool RES>
__global__ __launch_bounds__(256)
void gemm64(const float* __restrict__ A, const float* __restrict__ B,
            const float* __restrict__ bias, const float* __restrict__ res,
            float* __restrict__ C, int M, int N, int K)
{
    gemm_body<RELU, RES>(A, B, bias, res, C, M, N, K);
}

// fused QKV: blockIdx.z selects {Q,K,V}
__global__ __launch_bounds__(256)
void qkv_gemm(const float* __restrict__ row_emb, const float* __restrict__ col_emb,
              const float* __restrict__ Wq, const float* __restrict__ Wk,
              const float* __restrict__ Wv,
              float* __restrict__ q, float* __restrict__ k, float* __restrict__ v)
{
    const float* A; const float* B; float* C;
    if (blockIdx.z == 0)      { A = row_emb; B = Wq; C = q; }
    else if (blockIdx.z == 1) { A = col_emb; B = Wk; C = k; }
    else                      { A = col_emb; B = Wv; C = v; }
    gemm_body<false, false>(A, B, nullptr, nullptr, C, Bn * Rn, En, En);
}

// ---------------- fused attention ----------------
// grid: (B*H, R/16), block 256 (8 warps). Each warp: 2 rows. Online softmax
// over two 256-col halves. K/V in smem, 20-float row stride (LDS.128, conflict-free).
#define KV_STRIDE 20
#define ATTN_SMEM ((Cn * KV_STRIDE * 2 + 16 * Dn) * (int)sizeof(float))
#define ROWS_PER_BLK 16

__global__ __launch_bounds__(256, 2)
void attn_kernel(const float* __restrict__ Q, const float* __restrict__ K,
                 const float* __restrict__ V, const float* __restrict__ cost,
                 const float* __restrict__ mix1_w, const float* __restrict__ mix1_b,
                 const float* __restrict__ mix2_w, const float* __restrict__ mix2_b,
                 float* __restrict__ Out)
{
    extern __shared__ float sh[];
    float* ksh = sh;                         // 512 * 20
    float* vsh = sh + Cn * KV_STRIDE;        // 512 * 20
    float* qsh = vsh + Cn * KV_STRIDE;       // 16 * 16

    __shared__ float4 swp[Mn];   // {wd, wc, wb, w2} per m
    __shared__ float sb2;

    const int tid = threadIdx.x;
    const int b = blockIdx.x >> 4;
    const int h = blockIdx.x & 15;
    const int r0 = blockIdx.y * ROWS_PER_BLK;

    if (tid < Mn) {
        float4 w;
        w.x = mix1_w[h * 2 * Mn + tid];
        w.y = mix1_w[h * 2 * Mn + Mn + tid];
        w.z = mix1_b[h * Mn + tid];
        w.w = mix2_w[h * Mn + tid];
        swp[tid] = w;
    }
    if (tid == 0) sb2 = mix2_b[h];

    // K,V -> smem (transpose-free, stride 20), float4 per thread
    for (int idx = tid; idx < Cn * 4; idx += 256) {
        int c = idx >> 2, g = idx & 3;
        size_t src = ((size_t)(b * Cn + c)) * En + h * Dn + g * 4;
        *reinterpret_cast<float4*>(&ksh[c * KV_STRIDE + g * 4]) =
            *reinterpret_cast<const float4*>(&K[src]);
        *reinterpret_cast<float4*>(&vsh[c * KV_STRIDE + g * 4]) =
            *reinterpret_cast<const float4*>(&V[src]);
    }
    if (tid < ROWS_PER_BLK * Dn) {
        int rr = tid >> 4, d = tid & 15;
        qsh[tid] = Q[((size_t)(b * Rn + r0 + rr)) * En + h * Dn + d];
    }
    __syncthreads();

    const int warp = tid >> 5;
    const int lane = tid & 31;
    const float b2r = sb2;

    for (int rr = warp; rr < ROWS_PER_BLK; rr += 8) {
        const int r = r0 + rr;
        const float4 q0 = *reinterpret_cast<const float4*>(&qsh[rr * Dn + 0]);
        const float4 q1 = *reinterpret_cast<const float4*>(&qsh[rr * Dn + 4]);
        const float4 q2 = *reinterpret_cast<const float4*>(&qsh[rr * Dn + 8]);
        const float4 q3 = *reinterpret_cast<const float4*>(&qsh[rr * Dn + 12]);
        const float* crow = &cost[((size_t)(b * Rn + r)) * Cn];

        float o[16];
#pragma unroll
        for (int d = 0; d < 16; d++) o[d] = 0.0f;
        float m_run = -1e30f;
        float s_run = 0.0f;

#pragma unroll
        for (int half = 0; half < 2; half++) {
            float dotv[8], cv[8], mixed[8];
            // scores
#pragma unroll
            for (int i = 0; i < 8; i++) {
                int c = lane + 32 * (half * 8 + i);
                const float4* kp = reinterpret_cast<const float4*>(&ksh[c * KV_STRIDE]);
                float4 k0 = kp[0], k1 = kp[1], k2 = kp[2], k3 = kp[3];
                float acc;
                acc = q0.x * k0.x;
                acc = fmaf(q0.y, k0.y, acc); acc = fmaf(q0.z, k0.z, acc); acc = fmaf(q0.w, k0.w, acc);
                acc = fmaf(q1.x, k1.x, acc); acc = fmaf(q1.y, k1.y, acc); acc = fmaf(q1.z, k1.z, acc); acc = fmaf(q1.w, k1.w, acc);
                acc = fmaf(q2.x, k2.x, acc); acc = fmaf(q2.y, k2.y, acc); acc = fmaf(q2.z, k2.z, acc); acc = fmaf(q2.w, k2.w, acc);
                acc = fmaf(q3.x, k3.x, acc); acc = fmaf(q3.y, k3.y, acc); acc = fmaf(q3.z, k3.z, acc); acc = fmaf(q3.w, k3.w, acc);
                dotv[i] = acc * 0.25f;
                cv[i] = __ldg(&crow[c]);
                mixed[i] = b2r;
            }
            // mix MLP: 2 -> 16 relu -> 1
#pragma unroll
            for (int m = 0; m < Mn; m++) {
                float4 w = swp[m];
#pragma unroll
                for (int i = 0; i < 8; i++) {
                    float t = fmaf(dotv[i], w.x, fmaf(cv[i], w.y, w.z));
                    mixed[i] = fmaf(fmaxf(t, 0.0f), w.w, mixed[i]);
                }
            }
            // online softmax update
            float hm = mixed[0];
#pragma unroll
            for (int i = 1; i < 8; i++) hm = fmaxf(hm, mixed[i]);
#pragma unroll
            for (int off = 16; off; off >>= 1)
                hm = fmaxf(hm, __shfl_xor_sync(0xFFFFFFFFu, hm, off));
            float m_new = fmaxf(m_run, hm);
            float corr = __expf(m_run - m_new);
            s_run *= corr;
#pragma unroll
            for (int d = 0; d < 16; d++) o[d] *= corr;
            m_run = m_new;
            // exp + PV
#pragma unroll
            for (int i = 0; i < 8; i++) {
                int c = lane + 32 * (half * 8 + i);
                float e = __expf(mixed[i] - m_new);
                s_run += e;
                const float4* vp = reinterpret_cast<const float4*>(&vsh[c * KV_STRIDE]);
                float4 v0 = vp[0], v1 = vp[1], v2 = vp[2], v3 = vp[3];
                o[0]  = fmaf(e, v0.x, o[0]);  o[1]  = fmaf(e, v0.y, o[1]);
                o[2]  = fmaf(e, v0.z, o[2]);  o[3]  = fmaf(e, v0.w, o[3]);
                o[4]  = fmaf(e, v1.x, o[4]);  o[5]  = fmaf(e, v1.y, o[5]);
                o[6]  = fmaf(e, v1.z, o[6]);  o[7]  = fmaf(e, v1.w, o[7]);
                o[8]  = fmaf(e, v2.x, o[8]);  o[9]  = fmaf(e, v2.y, o[9]);
                o[10] = fmaf(e, v2.z, o[10]); o[11] = fmaf(e, v2.w, o[11]);
                o[12] = fmaf(e, v3.x, o[12]); o[13] = fmaf(e, v3.y, o[13]);
                o[14] = fmaf(e, v3.z, o[14]); o[15] = fmaf(e, v3.w, o[15]);
            }
        }

        // reductions
#pragma unroll
        for (int off = 16; off; off >>= 1)
            s_run += __shfl_xor_sync(0xFFFFFFFFu, s_run, off);
        const float inv = 1.0f / s_run;
#pragma unroll
        for (int d = 0; d < 16; d++) {
#pragma unroll
            for (int off = 16; off; off >>= 1)
                o[d] += __shfl_xor_sync(0xFFFFFFFFu, o[d], off);
        }
        if (lane < 16)
            Out[((size_t)(b * Rn + r)) * En + h * Dn + lane] = o[lane] * inv;
    }
}

// ---------------- instance norm ----------------
__global__ __launch_bounds__(256)
void inorm_kernel(const float* __restrict__ X, const float* __restrict__ gamma,
                  const float* __restrict__ beta, float* __restrict__ Y)
{
    const int b = blockIdx.y;
    const int e = blockIdx.x * 64 + threadIdx.x;
    const int ty = threadIdx.y;
    const float* xb = X + (size_t)b * Rn * En;
    float* yb = Y + (size_t)b * Rn * En;

    float s = 0.0f, s2 = 0.0f;
    for (int r = ty; r < Rn; r += 4) {
        float v = xb[(size_t)r * En + e];
        s += v; s2 += v * v;
    }
    __shared__ float ss[4][64], sq[4][64];
    __shared__ float sa[64], sb[64];
    ss[ty][threadIdx.x] = s;
    sq[ty][threadIdx.x] = s2;
    __syncthreads();
    if (ty == 0) {
        float t  = ss[0][threadIdx.x] + ss[1][threadIdx.x] + ss[2][threadIdx.x] + ss[3][threadIdx.x];
        float t2 = sq[0][threadIdx.x] + sq[1][threadIdx.x] + sq[2][threadIdx.x] + sq[3][threadIdx.x];
        float mean = t * (1.0f / Rn);
        float var  = t2 * (1.0f / Rn) - mean * mean;
        float rstd = rsqrtf(var + 1e-5f);
        float a = gamma[e] * rstd;
        sa[threadIdx.x] = a;
        sb[threadIdx.x] = beta[e] - mean * a;
    }
    __syncthreads();
    const float a = sa[threadIdx.x], bb = sb[threadIdx.x];
    for (int r = ty; r < Rn; r += 4)
        yb[(size_t)r * En + e] = fmaf(xb[(size_t)r * En + e], a, bb);
}

// ---------------- launch ----------------
extern "C" void kernel_launch(void* const* d_in, const int* in_sizes, int n_in,
                              void* d_out, int out_size)
{
    const float* row_emb = (const float*)d_in[0];
    const float* col_emb = (const float*)d_in[1];
    const float* cost    = (const float*)d_in[2];
    const float* Wq      = (const float*)d_in[3];
    const float* Wk      = (const float*)d_in[4];
    const float* Wv      = (const float*)d_in[5];
    const float* mix1_w  = (const float*)d_in[6];
    const float* mix1_b  = (const float*)d_in[7];
    const float* mix2_w  = (const float*)d_in[8];
    const float* mix2_b  = (const float*)d_in[9];
    const float* Wc      = (const float*)d_in[10];
    const float* bc      = (const float*)d_in[11];
    const float* W1      = (const float*)d_in[12];
    const float* b1      = (const float*)d_in[13];
    const float* W2      = (const float*)d_in[14];
    const float* b2      = (const float*)d_in[15];
    const float* g1      = (const float*)d_in[16];
    const float* be1     = (const float*)d_in[17];
    const float* g2      = (const float*)d_in[18];
    const float* be2     = (const float*)d_in[19];
    float* out = (float*)d_out;

    float *q, *k, *v, *att, *y, *x, *hh, *z;
    cudaGetSymbolAddress((void**)&q,   g_q);
    cudaGetSymbolAddress((void**)&k,   g_k);
    cudaGetSymbolAddress((void**)&v,   g_v);
    cudaGetSymbolAddress((void**)&att, g_att);
    cudaGetSymbolAddress((void**)&y,   g_y);
    cudaGetSymbolAddress((void**)&x,   g_x);
    cudaGetSymbolAddress((void**)&hh,  g_h);
    cudaGetSymbolAddress((void**)&z,   g_z);

    cudaFuncSetAttribute(attn_kernel, cudaFuncAttributeMaxDynamicSharedMemorySize, ATTN_SMEM);

    const int MR = Bn * Rn;   // 2048

    // fused QKV
    {
        dim3 g(En / 64, MR / 64, 3);
        qkv_gemm<<<g, 256>>>(row_emb, col_emb, Wq, Wk, Wv, q, k, v);
    }

    // fused attention
    {
        dim3 g(Bn * Hn, Rn / ROWS_PER_BLK);
        attn_kernel<<<g, 256, ATTN_SMEM>>>(q, k, v, cost, mix1_w, mix1_b, mix2_w, mix2_b, att);
    }

    // combine + residual
    {
        dim3 g(En / 64, MR / 64);
        gemm64<false, true><<<g, 256>>>(att, Wc, bc, row_emb, y, MR, En, En);
    }
    // norm1
    {
        dim3 g(En / 64, Bn);
        inorm_kernel<<<g, dim3(64, 4)>>>(y, g1, be1, x);
    }
    // FFN
    {
        dim3 ga(Fn / 64, MR / 64);
        gemm64<true, false><<<ga, 256>>>(x, W1, b1, nullptr, hh, MR, Fn, En);
        dim3 gb(En / 64, MR / 64);
        gemm64<false, true><<<gb, 256>>>(hh, W2, b2, x, z, MR, En, Fn);
    }
    // norm2 -> out
    {
        dim3 g(En / 64, Bn);
        inorm_kernel<<<g, dim3(64, 4)>>>(z, g2, be2, out);
    }
}

// round 4
// speedup vs baseline: 2.0956x; 1.0741x over previous
#include <cuda_runtime.h>
#include <math.h>

#define Bn 4
#define Rn 512
#define Cn 512
#define En 256
#define Hn 16
#define Dn 16
#define Mn 16
#define Fn 512

// ---------------- packed f32x2 helpers (sm_103a FFMA2) ----------------
typedef unsigned long long u64;
struct __align__(16) U2 { u64 a, b; };

__device__ __forceinline__ u64 pk(float lo, float hi) {
    u64 r; asm("mov.b64 %0,{%1,%2};" : "=l"(r) : "f"(lo), "f"(hi)); return r;
}
__device__ __forceinline__ void upk(u64 v, float& lo, float& hi) {
    asm("mov.b64 {%0,%1},%2;" : "=f"(lo), "=f"(hi) : "l"(v));
}
__device__ __forceinline__ u64 fma2(u64 a, u64 b, u64 c) {
    u64 d; asm("fma.rn.f32x2 %0,%1,%2,%3;" : "=l"(d) : "l"(a), "l"(b), "l"(c)); return d;
}
__device__ __forceinline__ u64 mul2(u64 a, u64 b) {
    u64 d; asm("mul.rn.f32x2 %0,%1,%2;" : "=l"(d) : "l"(a), "l"(b)); return d;
}

// ---------------- scratch ----------------
__device__ float g_q[Bn*Rn*En];
__device__ float g_k[Bn*Cn*En];
__device__ float g_v[Bn*Cn*En];
__device__ float g_att[Bn*Rn*En];
__device__ float g_y[Bn*Rn*En];
__device__ float g_x[Bn*Rn*En];
__device__ float g_h[Bn*Rn*Fn];
__device__ float g_z[Bn*Rn*En];

// ---------------- SGEMM body (BM=BN=64, BK=16, 256 thr, 4x4 micro, f32x2) ----------------
template<bool RELU, bool RES>
__device__ __forceinline__
void gemm_body(const float* __restrict__ A, const float* __restrict__ B,
               const float* __restrict__ bias, const float* __restrict__ res,
               float* __restrict__ C, int M, int N, int K)
{
    __shared__ float As[16][64];
    __shared__ float Bs[16][64];
    const int tid = threadIdx.x;
    const int tx = tid & 15;
    const int ty = tid >> 4;
    const int m0 = blockIdx.y * 64;
    const int n0 = blockIdx.x * 64;

    const int arow = tid >> 2;
    const int acol = (tid & 3) * 4;
    const int brow = tid >> 4;
    const int bcol = (tid & 15) * 4;

    u64 acc2[4][2] = {};   // 4 m-rows x 2 packed n-pairs

    for (int k0 = 0; k0 < K; k0 += 16) {
        float4 av = *reinterpret_cast<const float4*>(&A[(size_t)(m0 + arow) * K + k0 + acol]);
        float4 bv = *reinterpret_cast<const float4*>(&B[(size_t)(k0 + brow) * N + n0 + bcol]);
        __syncthreads();
        As[acol + 0][arow] = av.x;
        As[acol + 1][arow] = av.y;
        As[acol + 2][arow] = av.z;
        As[acol + 3][arow] = av.w;
        *reinterpret_cast<float4*>(&Bs[brow][bcol]) = bv;
        __syncthreads();
#pragma unroll
        for (int k = 0; k < 16; k++) {
            float4 a4 = *reinterpret_cast<const float4*>(&As[k][ty * 4]);
            float4 b4 = *reinterpret_cast<const float4*>(&Bs[k][tx * 4]);
            u64 b01 = pk(b4.x, b4.y);
            u64 b23 = pk(b4.z, b4.w);
            u64 a0 = pk(a4.x, a4.x), a1 = pk(a4.y, a4.y);
            u64 a2 = pk(a4.z, a4.z), a3 = pk(a4.w, a4.w);
            acc2[0][0] = fma2(a0, b01, acc2[0][0]); acc2[0][1] = fma2(a0, b23, acc2[0][1]);
            acc2[1][0] = fma2(a1, b01, acc2[1][0]); acc2[1][1] = fma2(a1, b23, acc2[1][1]);
            acc2[2][0] = fma2(a2, b01, acc2[2][0]); acc2[2][1] = fma2(a2, b23, acc2[2][1]);
            acc2[3][0] = fma2(a3, b01, acc2[3][0]); acc2[3][1] = fma2(a3, b23, acc2[3][1]);
        }
    }

#pragma unroll
    for (int i = 0; i < 4; i++) {
        int m = m0 + ty * 4 + i;
        float c0, c1, c2, c3;
        upk(acc2[i][0], c0, c1);
        upk(acc2[i][1], c2, c3);
        float vals[4] = {c0, c1, c2, c3};
#pragma unroll
        for (int j = 0; j < 4; j++) {
            int n = n0 + tx * 4 + j;
            float v = vals[j];
            if (bias) v += bias[n];
            if (RES)  v += res[(size_t)m * N + n];
            if (RELU) v = fmaxf(v, 0.0f);
            C[(size_t)m * N + n] = v;
        }
    }
}

template<bool RELU, bool RES>
__global__ __launch_bounds__(256)
void gemm64(const float* __restrict__ A, const float* __restrict__ B,
            const float* __restrict__ bias, const float* __restrict__ res,
            float* __restrict__ C, int M, int N, int K)
{
    gemm_body<RELU, RES>(A, B, bias, res, C, M, N, K);
}

__global__ __launch_bounds__(256)
void qkv_gemm(const float* __restrict__ row_emb, const float* __restrict__ col_emb,
              const float* __restrict__ Wq, const float* __restrict__ Wk,
              const float* __restrict__ Wv,
              float* __restrict__ q, float* __restrict__ k, float* __restrict__ v)
{
    const float* A; const float* B; float* C;
    if (blockIdx.z == 0)      { A = row_emb; B = Wq; C = q; }
    else if (blockIdx.z == 1) { A = col_emb; B = Wk; C = k; }
    else                      { A = col_emb; B = Wv; C = v; }
    gemm_body<false, false>(A, B, nullptr, nullptr, C, Bn * Rn, En, En);
}

// ---------------- fused attention ----------------
// grid (B*H, R/16), 256 thr (8 warps). Each warp owns rows (r0+w, r0+w+8),
// processed JOINTLY so K/V smem loads are shared. All heavy math in f32x2.
// Online softmax over 4 stages of 128 columns.
#define KV_STRIDE 20
#define ATTN_SMEM ((Cn * KV_STRIDE * 2 + 16 * Dn) * (int)sizeof(float))
#define ROWS_PER_BLK 16
#define CHUNK 4

__global__ __launch_bounds__(256, 2)
void attn_kernel(const float* __restrict__ Q, const float* __restrict__ K,
                 const float* __restrict__ V, const float* __restrict__ cost,
                 const float* __restrict__ mix1_w, const float* __restrict__ mix1_b,
                 const float* __restrict__ mix2_w, const float* __restrict__ mix2_b,
                 float* __restrict__ Out)
{
    extern __shared__ float sh[];
    float* ksh = sh;                        // 512 x 20
    float* vsh = sh + Cn * KV_STRIDE;       // 512 x 20
    float* qsh = vsh + Cn * KV_STRIDE;      // 16 x 16

    __shared__ U2 swA[Mn];    // {wd packed, wc packed}
    __shared__ U2 swB[Mn];    // {wb packed, w2 packed}
    __shared__ float sb2;

    const int tid = threadIdx.x;
    const int b = blockIdx.x >> 4;
    const int h = blockIdx.x & 15;
    const int r0 = blockIdx.y * ROWS_PER_BLK;

    if (tid < Mn) {
        float wd = mix1_w[h * 2 * Mn + tid];
        float wc = mix1_w[h * 2 * Mn + Mn + tid];
        float wb = mix1_b[h * Mn + tid];
        float w2 = mix2_w[h * Mn + tid];
        swA[tid].a = pk(wd, wd);
        swA[tid].b = pk(wc, wc);
        swB[tid].a = pk(wb, wb);
        swB[tid].b = pk(w2, w2);
    }
    if (tid == 0) sb2 = mix2_b[h];

    for (int idx = tid; idx < Cn * 4; idx += 256) {
        int c = idx >> 2, g = idx & 3;
        size_t src = ((size_t)(b * Cn + c)) * En + h * Dn + g * 4;
        *reinterpret_cast<float4*>(&ksh[c * KV_STRIDE + g * 4]) =
            *reinterpret_cast<const float4*>(&K[src]);
        *reinterpret_cast<float4*>(&vsh[c * KV_STRIDE + g * 4]) =
            *reinterpret_cast<const float4*>(&V[src]);
    }
    if (tid < ROWS_PER_BLK * Dn) {
        int rr = tid >> 4, d = tid & 15;
        qsh[tid] = Q[((size_t)(b * Rn + r0 + rr)) * En + h * Dn + d];
    }
    __syncthreads();

    const int warp = tid >> 5;
    const int lane = tid & 31;
    const int ra = r0 + warp;
    const int rb = r0 + warp + 8;

    // Q rows as packed d-pairs
    u64 qa[8], qb[8];
    {
        const u64* pa = reinterpret_cast<const u64*>(&qsh[warp * Dn]);
        const u64* pb = reinterpret_cast<const u64*>(&qsh[(warp + 8) * Dn]);
#pragma unroll
        for (int j = 0; j < 8; j++) { qa[j] = pa[j]; qb[j] = pb[j]; }
    }

    const float* crA = &cost[((size_t)(b * Rn + ra)) * Cn];
    const float* crB = &cost[((size_t)(b * Rn + rb)) * Cn];

    u64 oa[8] = {}, ob[8] = {};
    float mra = -1e30f, mrb = -1e30f, ssa = 0.0f, ssb = 0.0f;
    const u64 binit = pk(sb2, sb2);

#pragma unroll
    for (int st = 0; st < 4; st++) {
        u64 dot2[CHUNK], cv2[CHUNK], mx2[CHUNK];
        // --- scores (both rows share K loads) ---
#pragma unroll
        for (int i = 0; i < CHUNK; i++) {
            int c = lane + 32 * (st * CHUNK + i);
            const U2* kp = reinterpret_cast<const U2*>(&ksh[c * KV_STRIDE]);
            U2 k01 = kp[0], k23 = kp[1];
            u64 aA = 0, aB = 0;
            aA = fma2(qa[0], k01.a, aA); aB = fma2(qb[0], k01.a, aB);
            aA = fma2(qa[1], k01.b, aA); aB = fma2(qb[1], k01.b, aB);
            aA = fma2(qa[2], k23.a, aA); aB = fma2(qb[2], k23.a, aB);
            aA = fma2(qa[3], k23.b, aA); aB = fma2(qb[3], k23.b, aB);
            U2 k45 = kp[2], k67 = kp[3];
            aA = fma2(qa[4], k45.a, aA); aB = fma2(qb[4], k45.a, aB);
            aA = fma2(qa[5], k45.b, aA); aB = fma2(qb[5], k45.b, aB);
            aA = fma2(qa[6], k67.a, aA); aB = fma2(qb[6], k67.a, aB);
            aA = fma2(qa[7], k67.b, aA); aB = fma2(qb[7], k67.b, aB);
            float x0, x1, y0, y1;
            upk(aA, x0, x1); upk(aB, y0, y1);
            dot2[i] = pk((x0 + x1) * 0.25f, (y0 + y1) * 0.25f);
            cv2[i]  = pk(__ldg(&crA[c]), __ldg(&crB[c]));
            mx2[i]  = binit;
        }
        // --- mix MLP: 2 -> 16 relu -> 1, both rows packed ---
#pragma unroll
        for (int m = 0; m < Mn; m++) {
            U2 w1 = swA[m];
            U2 w2w = swB[m];
#pragma unroll
            for (int i = 0; i < CHUNK; i++) {
                u64 t = fma2(dot2[i], w1.a, fma2(cv2[i], w1.b, w2w.a));
                float t0, t1; upk(t, t0, t1);
                t0 = fmaxf(t0, 0.0f); t1 = fmaxf(t1, 0.0f);
                mx2[i] = fma2(pk(t0, t1), w2w.b, mx2[i]);
            }
        }
        // --- online softmax update ---
        float mxa[CHUNK], mxb[CHUNK];
        float ha = -1e30f, hb = -1e30f;
#pragma unroll
        for (int i = 0; i < CHUNK; i++) {
            upk(mx2[i], mxa[i], mxb[i]);
            ha = fmaxf(ha, mxa[i]); hb = fmaxf(hb, mxb[i]);
        }
#pragma unroll
        for (int off = 16; off; off >>= 1) {
            ha = fmaxf(ha, __shfl_xor_sync(0xFFFFFFFFu, ha, off));
            hb = fmaxf(hb, __shfl_xor_sync(0xFFFFFFFFu, hb, off));
        }
        float mna = fmaxf(mra, ha), mnb = fmaxf(mrb, hb);
        float ca = __expf(mra - mna), cb = __expf(mrb - mnb);
        ssa *= ca; ssb *= cb;
        u64 ca2 = pk(ca, ca), cb2 = pk(cb, cb);
#pragma unroll
        for (int j = 0; j < 8; j++) { oa[j] = mul2(oa[j], ca2); ob[j] = mul2(ob[j], cb2); }
        mra = mna; mrb = mnb;
        // --- exp + PV (both rows share V loads) ---
#pragma unroll
        for (int i = 0; i < CHUNK; i++) {
            int c = lane + 32 * (st * CHUNK + i);
            float ea = __expf(mxa[i] - mra);
            float eb = __expf(mxb[i] - mrb);
            ssa += ea; ssb += eb;
            const U2* vp = reinterpret_cast<const U2*>(&vsh[c * KV_STRIDE]);
            U2 v01 = vp[0], v23 = vp[1], v45 = vp[2], v67 = vp[3];
            u64 ea2 = pk(ea, ea), eb2 = pk(eb, eb);
            oa[0] = fma2(ea2, v01.a, oa[0]); ob[0] = fma2(eb2, v01.a, ob[0]);
            oa[1] = fma2(ea2, v01.b, oa[1]); ob[1] = fma2(eb2, v01.b, ob[1]);
            oa[2] = fma2(ea2, v23.a, oa[2]); ob[2] = fma2(eb2, v23.a, ob[2]);
            oa[3] = fma2(ea2, v23.b, oa[3]); ob[3] = fma2(eb2, v23.b, ob[3]);
            oa[4] = fma2(ea2, v45.a, oa[4]); ob[4] = fma2(eb2, v45.a, ob[4]);
            oa[5] = fma2(ea2, v45.b, oa[5]); ob[5] = fma2(eb2, v45.b, ob[5]);
            oa[6] = fma2(ea2, v67.a, oa[6]); ob[6] = fma2(eb2, v67.a, ob[6]);
            oa[7] = fma2(ea2, v67.b, oa[7]); ob[7] = fma2(eb2, v67.b, ob[7]);
        }
    }

    // --- final reductions ---
#pragma unroll
    for (int off = 16; off; off >>= 1) {
        ssa += __shfl_xor_sync(0xFFFFFFFFu, ssa, off);
        ssb += __shfl_xor_sync(0xFFFFFFFFu, ssb, off);
    }
    const float inva = 1.0f / ssa;
    const float invb = 1.0f / ssb;

    float outa[16], outb[16];
#pragma unroll
    for (int j = 0; j < 8; j++) {
        upk(oa[j], outa[2 * j], outa[2 * j + 1]);
        upk(ob[j], outb[2 * j], outb[2 * j + 1]);
    }
#pragma unroll
    for (int d = 0; d < 16; d++) {
#pragma unroll
        for (int off = 16; off; off >>= 1) {
            outa[d] += __shfl_xor_sync(0xFFFFFFFFu, outa[d], off);
            outb[d] += __shfl_xor_sync(0xFFFFFFFFu, outb[d], off);
        }
    }
    if (lane < 16) {
        Out[((size_t)(b * Rn + ra)) * En + h * Dn + lane] = outa[lane] * inva;
        Out[((size_t)(b * Rn + rb)) * En + h * Dn + lane] = outb[lane] * invb;
    }
}

// ---------------- instance norm: grid (E/16, B), block (16,16) ----------------
__global__ __launch_bounds__(256)
void inorm_kernel(const float* __restrict__ X, const float* __restrict__ gamma,
                  const float* __restrict__ beta, float* __restrict__ Y)
{
    const int b = blockIdx.y;
    const int tx = threadIdx.x;            // e within chunk
    const int ty = threadIdx.y;            // r stride
    const int e = blockIdx.x * 16 + tx;
    const float* xb = X + (size_t)b * Rn * En;
    float* yb = Y + (size_t)b * Rn * En;

    float s = 0.0f, s2 = 0.0f;
    for (int r = ty; r < Rn; r += 16) {
        float v = xb[(size_t)r * En + e];
        s += v; s2 += v * v;
    }
    __shared__ float ss[16][17], sq[16][17];
    __shared__ float sa_[16], sbb[16];
    ss[ty][tx] = s;
    sq[ty][tx] = s2;
    __syncthreads();
    if (ty == 0) {
        float t = 0.0f, t2 = 0.0f;
#pragma unroll
        for (int j = 0; j < 16; j++) { t += ss[j][tx]; t2 += sq[j][tx]; }
        float mean = t * (1.0f / Rn);
        float var  = t2 * (1.0f / Rn) - mean * mean;
        float rstd = rsqrtf(var + 1e-5f);
        float a = gamma[e] * rstd;
        sa_[tx] = a;
        sbb[tx] = beta[e] - mean * a;
    }
    __syncthreads();
    const float a = sa_[tx], bb = sbb[tx];
    for (int r = ty; r < Rn; r += 16)
        yb[(size_t)r * En + e] = fmaf(xb[(size_t)r * En + e], a, bb);
}

// ---------------- launch ----------------
extern "C" void kernel_launch(void* const* d_in, const int* in_sizes, int n_in,
                              void* d_out, int out_size)
{
    const float* row_emb = (const float*)d_in[0];
    const float* col_emb = (const float*)d_in[1];
    const float* cost    = (const float*)d_in[2];
    const float* Wq      = (const float*)d_in[3];
    const float* Wk      = (const float*)d_in[4];
    const float* Wv      = (const float*)d_in[5];
    const float* mix1_w  = (const float*)d_in[6];
    const float* mix1_b  = (const float*)d_in[7];
    const float* mix2_w  = (const float*)d_in[8];
    const float* mix2_b  = (const float*)d_in[9];
    const float* Wc      = (const float*)d_in[10];
    const float* bc      = (const float*)d_in[11];
    const float* W1      = (const float*)d_in[12];
    const float* b1      = (const float*)d_in[13];
    const float* W2      = (const float*)d_in[14];
    const float* b2      = (const float*)d_in[15];
    const float* g1      = (const float*)d_in[16];
    const float* be1     = (const float*)d_in[17];
    const float* g2      = (const float*)d_in[18];
    const float* be2     = (const float*)d_in[19];
    float* out = (float*)d_out;

    float *q, *k, *v, *att, *y, *x, *hh, *z;
    cudaGetSymbolAddress((void**)&q,   g_q);
    cudaGetSymbolAddress((void**)&k,   g_k);
    cudaGetSymbolAddress((void**)&v,   g_v);
    cudaGetSymbolAddress((void**)&att, g_att);
    cudaGetSymbolAddress((void**)&y,   g_y);
    cudaGetSymbolAddress((void**)&x,   g_x);
    cudaGetSymbolAddress((void**)&hh,  g_h);
    cudaGetSymbolAddress((void**)&z,   g_z);

    cudaFuncSetAttribute(attn_kernel, cudaFuncAttributeMaxDynamicSharedMemorySize, ATTN_SMEM);

    const int MR = Bn * Rn;   // 2048

    {   // fused QKV
        dim3 g(En / 64, MR / 64, 3);
        qkv_gemm<<<g, 256>>>(row_emb, col_emb, Wq, Wk, Wv, q, k, v);
    }
    {   // fused attention
        dim3 g(Bn * Hn, Rn / ROWS_PER_BLK);
        attn_kernel<<<g, 256, ATTN_SMEM>>>(q, k, v, cost, mix1_w, mix1_b, mix2_w, mix2_b, att);
    }
    {   // combine + residual
        dim3 g(En / 64, MR / 64);
        gemm64<false, true><<<g, 256>>>(att, Wc, bc, row_emb, y, MR, En, En);
    }
    {   // norm1
        dim3 g(En / 16, Bn);
        inorm_kernel<<<g, dim3(16, 16)>>>(y, g1, be1, x);
    }
    {   // FFN
        dim3 ga(Fn / 64, MR / 64);
        gemm64<true, false><<<ga, 256>>>(x, W1, b1, nullptr, hh, MR, Fn, En);
        dim3 gb(En / 64, MR / 64);
        gemm64<false, true><<<gb, 256>>>(hh, W2, b2, x, z, MR, En, Fn);
    }
    {   // norm2 -> out
        dim3 g(En / 16, Bn);
        inorm_kernel<<<g, dim3(16, 16)>>>(z, g2, be2, out);
    }
}

// round 5
// speedup vs baseline: 2.0959x; 1.0001x over previous
#include <cuda_runtime.h>
#include <math.h>

#define Bn 4
#define Rn 512
#define Cn 512
#define En 256
#define Hn 16
#define Dn 16
#define Mn 16
#define Fn 512

// ---------------- packed f32x2 helpers (sm_103a FFMA2) ----------------
typedef unsigned long long u64;
struct __align__(16) U2 { u64 a, b; };

__device__ __forceinline__ u64 pk(float lo, float hi) {
    u64 r; asm("mov.b64 %0,{%1,%2};" : "=l"(r) : "f"(lo), "f"(hi)); return r;
}
__device__ __forceinline__ void upk(u64 v, float& lo, float& hi) {
    asm("mov.b64 {%0,%1},%2;" : "=f"(lo), "=f"(hi) : "l"(v));
}
__device__ __forceinline__ u64 fma2(u64 a, u64 b, u64 c) {
    u64 d; asm("fma.rn.f32x2 %0,%1,%2,%3;" : "=l"(d) : "l"(a), "l"(b), "l"(c)); return d;
}
__device__ __forceinline__ u64 mul2(u64 a, u64 b) {
    u64 d; asm("mul.rn.f32x2 %0,%1,%2;" : "=l"(d) : "l"(a), "l"(b)); return d;
}

// ---------------- scratch ----------------
__device__ float g_q[Bn*Rn*En];
__device__ float g_k[Bn*Cn*En];
__device__ float g_v[Bn*Cn*En];
__device__ float g_att[Bn*Rn*En];
__device__ float g_y[Bn*Rn*En];
__device__ float g_x[Bn*Rn*En];
__device__ float g_h[Bn*Rn*Fn];
__device__ float g_z[Bn*Rn*En];

// ---------------- SGEMM body (BM=BN=64, BK=16, 256 thr, 4x4 micro, f32x2) ----------------
template<bool RELU, bool RES>
__device__ __forceinline__
void gemm_body(const float* __restrict__ A, const float* __restrict__ B,
               const float* __restrict__ bias, const float* __restrict__ res,
               float* __restrict__ C, int M, int N, int K)
{
    __shared__ float As[16][64];
    __shared__ float Bs[16][64];
    const int tid = threadIdx.x;
    const int tx = tid & 15;
    const int ty = tid >> 4;
    const int m0 = blockIdx.y * 64;
    const int n0 = blockIdx.x * 64;

    const int arow = tid >> 2;
    const int acol = (tid & 3) * 4;
    const int brow = tid >> 4;
    const int bcol = (tid & 15) * 4;

    u64 acc2[4][2] = {};   // 4 m-rows x 2 packed n-pairs

    for (int k0 = 0; k0 < K; k0 += 16) {
        float4 av = *reinterpret_cast<const float4*>(&A[(size_t)(m0 + arow) * K + k0 + acol]);
        float4 bv = *reinterpret_cast<const float4*>(&B[(size_t)(k0 + brow) * N + n0 + bcol]);
        __syncthreads();
        As[acol + 0][arow] = av.x;
        As[acol + 1][arow] = av.y;
        As[acol + 2][arow] = av.z;
        As[acol + 3][arow] = av.w;
        *reinterpret_cast<float4*>(&Bs[brow][bcol]) = bv;
        __syncthreads();
#pragma unroll
        for (int k = 0; k < 16; k++) {
            float4 a4 = *reinterpret_cast<const float4*>(&As[k][ty * 4]);
            float4 b4 = *reinterpret_cast<const float4*>(&Bs[k][tx * 4]);
            u64 b01 = pk(b4.x, b4.y);
            u64 b23 = pk(b4.z, b4.w);
            u64 a0 = pk(a4.x, a4.x), a1 = pk(a4.y, a4.y);
            u64 a2 = pk(a4.z, a4.z), a3 = pk(a4.w, a4.w);
            acc2[0][0] = fma2(a0, b01, acc2[0][0]); acc2[0][1] = fma2(a0, b23, acc2[0][1]);
            acc2[1][0] = fma2(a1, b01, acc2[1][0]); acc2[1][1] = fma2(a1, b23, acc2[1][1]);
            acc2[2][0] = fma2(a2, b01, acc2[2][0]); acc2[2][1] = fma2(a2, b23, acc2[2][1]);
            acc2[3][0] = fma2(a3, b01, acc2[3][0]); acc2[3][1] = fma2(a3, b23, acc2[3][1]);
        }
    }

#pragma unroll
    for (int i = 0; i < 4; i++) {
        int m = m0 + ty * 4 + i;
        float c0, c1, c2, c3;
        upk(acc2[i][0], c0, c1);
        upk(acc2[i][1], c2, c3);
        float vals[4] = {c0, c1, c2, c3};
#pragma unroll
        for (int j = 0; j < 4; j++) {
            int n = n0 + tx * 4 + j;
            float v = vals[j];
            if (bias) v += bias[n];
            if (RES)  v += res[(size_t)m * N + n];
            if (RELU) v = fmaxf(v, 0.0f);
            C[(size_t)m * N + n] = v;
        }
    }
}

template<bool RELU, bool RES>
__global__ __launch_bounds__(256)
void gemm64(const float* __restrict__ A, const float* __restrict__ B,
            const float* __restrict__ bias, const float* __restrict__ res,
            float* __restrict__ C, int M, int N, int K)
{
    gemm_body<RELU, RES>(A, B, bias, res, C, M, N, K);
}

__global__ __launch_bounds__(256)
void qkv_gemm(const float* __restrict__ row_emb, const float* __restrict__ col_emb,
              const float* __restrict__ Wq, const float* __restrict__ Wk,
              const float* __restrict__ Wv,
              float* __restrict__ q, float* __restrict__ k, float* __restrict__ v)
{
    const float* A; const float* B; float* C;
    if (blockIdx.z == 0)      { A = row_emb; B = Wq; C = q; }
    else if (blockIdx.z == 1) { A = col_emb; B = Wk; C = k; }
    else                      { A = col_emb; B = Wv; C = v; }
    gemm_body<false, false>(A, B, nullptr, nullptr, C, Bn * Rn, En, En);
}

// ---------------- fused attention ----------------
// grid (B*H, R/16), 256 thr (8 warps). Each warp owns rows (r0+w, r0+w+8),
// processed JOINTLY so K/V smem loads are shared. All heavy math in f32x2.
// Online softmax over 4 stages of 128 columns.
#define KV_STRIDE 20
#define ATTN_SMEM ((Cn * KV_STRIDE * 2 + 16 * Dn) * (int)sizeof(float))
#define ROWS_PER_BLK 16
#define CHUNK 4

__global__ __launch_bounds__(256, 2)
void attn_kernel(const float* __restrict__ Q, const float* __restrict__ K,
                 const float* __restrict__ V, const float* __restrict__ cost,
                 const float* __restrict__ mix1_w, const float* __restrict__ mix1_b,
                 const float* __restrict__ mix2_w, const float* __restrict__ mix2_b,
                 float* __restrict__ Out)
{
    extern __shared__ float sh[];
    float* ksh = sh;                        // 512 x 20
    float* vsh = sh + Cn * KV_STRIDE;       // 512 x 20
    float* qsh = vsh + Cn * KV_STRIDE;      // 16 x 16

    __shared__ U2 swA[Mn];    // {wd packed, wc packed}
    __shared__ U2 swB[Mn];    // {wb packed, w2 packed}
    __shared__ float sb2;

    const int tid = threadIdx.x;
    const int b = blockIdx.x >> 4;
    const int h = blockIdx.x & 15;
    const int r0 = blockIdx.y * ROWS_PER_BLK;

    if (tid < Mn) {
        float wd = mix1_w[h * 2 * Mn + tid];
        float wc = mix1_w[h * 2 * Mn + Mn + tid];
        float wb = mix1_b[h * Mn + tid];
        float w2 = mix2_w[h * Mn + tid];
        swA[tid].a = pk(wd, wd);
        swA[tid].b = pk(wc, wc);
        swB[tid].a = pk(wb, wb);
        swB[tid].b = pk(w2, w2);
    }
    if (tid == 0) sb2 = mix2_b[h];

    for (int idx = tid; idx < Cn * 4; idx += 256) {
        int c = idx >> 2, g = idx & 3;
        size_t src = ((size_t)(b * Cn + c)) * En + h * Dn + g * 4;
        *reinterpret_cast<float4*>(&ksh[c * KV_STRIDE + g * 4]) =
            *reinterpret_cast<const float4*>(&K[src]);
        *reinterpret_cast<float4*>(&vsh[c * KV_STRIDE + g * 4]) =
            *reinterpret_cast<const float4*>(&V[src]);
    }
    if (tid < ROWS_PER_BLK * Dn) {
        int rr = tid >> 4, d = tid & 15;
        qsh[tid] = Q[((size_t)(b * Rn + r0 + rr)) * En + h * Dn + d];
    }
    __syncthreads();

    const int warp = tid >> 5;
    const int lane = tid & 31;
    const int ra = r0 + warp;
    const int rb = r0 + warp + 8;

    // Q rows as packed d-pairs
    u64 qa[8], qb[8];
    {
        const u64* pa = reinterpret_cast<const u64*>(&qsh[warp * Dn]);
        const u64* pb = reinterpret_cast<const u64*>(&qsh[(warp + 8) * Dn]);
#pragma unroll
        for (int j = 0; j < 8; j++) { qa[j] = pa[j]; qb[j] = pb[j]; }
    }

    const float* crA = &cost[((size_t)(b * Rn + ra)) * Cn];
    const float* crB = &cost[((size_t)(b * Rn + rb)) * Cn];

    u64 oa[8] = {}, ob[8] = {};
    float mra = -1e30f, mrb = -1e30f, ssa = 0.0f, ssb = 0.0f;
    const u64 binit = pk(sb2, sb2);

#pragma unroll
    for (int st = 0; st < 4; st++) {
        u64 dot2[CHUNK], cv2[CHUNK], mx2[CHUNK];
        // --- scores (both rows share K loads) ---
#pragma unroll
        for (int i = 0; i < CHUNK; i++) {
            int c = lane + 32 * (st * CHUNK + i);
            const U2* kp = reinterpret_cast<const U2*>(&ksh[c * KV_STRIDE]);
            U2 k01 = kp[0], k23 = kp[1];
            u64 aA = 0, aB = 0;
            aA = fma2(qa[0], k01.a, aA); aB = fma2(qb[0], k01.a, aB);
            aA = fma2(qa[1], k01.b, aA); aB = fma2(qb[1], k01.b, aB);
            aA = fma2(qa[2], k23.a, aA); aB = fma2(qb[2], k23.a, aB);
            aA = fma2(qa[3], k23.b, aA); aB = fma2(qb[3], k23.b, aB);
            U2 k45 = kp[2], k67 = kp[3];
            aA = fma2(qa[4], k45.a, aA); aB = fma2(qb[4], k45.a, aB);
            aA = fma2(qa[5], k45.b, aA); aB = fma2(qb[5], k45.b, aB);
            aA = fma2(qa[6], k67.a, aA); aB = fma2(qb[6], k67.a, aB);
            aA = fma2(qa[7], k67.b, aA); aB = fma2(qb[7], k67.b, aB);
            float x0, x1, y0, y1;
            upk(aA, x0, x1); upk(aB, y0, y1);
            dot2[i] = pk((x0 + x1) * 0.25f, (y0 + y1) * 0.25f);
            cv2[i]  = pk(__ldg(&crA[c]), __ldg(&crB[c]));
            mx2[i]  = binit;
        }
        // --- mix MLP: 2 -> 16 relu -> 1, both rows packed ---
#pragma unroll
        for (int m = 0; m < Mn; m++) {
            U2 w1 = swA[m];
            U2 w2w = swB[m];
#pragma unroll
            for (int i = 0; i < CHUNK; i++) {
                u64 t = fma2(dot2[i], w1.a, fma2(cv2[i], w1.b, w2w.a));
                float t0, t1; upk(t, t0, t1);
                t0 = fmaxf(t0, 0.0f); t1 = fmaxf(t1, 0.0f);
                mx2[i] = fma2(pk(t0, t1), w2w.b, mx2[i]);
            }
        }
        // --- online softmax update ---
        float mxa[CHUNK], mxb[CHUNK];
        float ha = -1e30f, hb = -1e30f;
#pragma unroll
        for (int i = 0; i < CHUNK; i++) {
            upk(mx2[i], mxa[i], mxb[i]);
            ha = fmaxf(ha, mxa[i]); hb = fmaxf(hb, mxb[i]);
        }
#pragma unroll
        for (int off = 16; off; off >>= 1) {
            ha = fmaxf(ha, __shfl_xor_sync(0xFFFFFFFFu, ha, off));
            hb = fmaxf(hb, __shfl_xor_sync(0xFFFFFFFFu, hb, off));
        }
        float mna = fmaxf(mra, ha), mnb = fmaxf(mrb, hb);
        float ca = __expf(mra - mna), cb = __expf(mrb - mnb);
        ssa *= ca; ssb *= cb;
        u64 ca2 = pk(ca, ca), cb2 = pk(cb, cb);
#pragma unroll
        for (int j = 0; j < 8; j++) { oa[j] = mul2(oa[j], ca2); ob[j] = mul2(ob[j], cb2); }
        mra = mna; mrb = mnb;
        // --- exp + PV (both rows share V loads) ---
#pragma unroll
        for (int i = 0; i < CHUNK; i++) {
            int c = lane + 32 * (st * CHUNK + i);
            float ea = __expf(mxa[i] - mra);
            float eb = __expf(mxb[i] - mrb);
            ssa += ea; ssb += eb;
            const U2* vp = reinterpret_cast<const U2*>(&vsh[c * KV_STRIDE]);
            U2 v01 = vp[0], v23 = vp[1], v45 = vp[2], v67 = vp[3];
            u64 ea2 = pk(ea, ea), eb2 = pk(eb, eb);
            oa[0] = fma2(ea2, v01.a, oa[0]); ob[0] = fma2(eb2, v01.a, ob[0]);
            oa[1] = fma2(ea2, v01.b, oa[1]); ob[1] = fma2(eb2, v01.b, ob[1]);
            oa[2] = fma2(ea2, v23.a, oa[2]); ob[2] = fma2(eb2, v23.a, ob[2]);
            oa[3] = fma2(ea2, v23.b, oa[3]); ob[3] = fma2(eb2, v23.b, ob[3]);
            oa[4] = fma2(ea2, v45.a, oa[4]); ob[4] = fma2(eb2, v45.a, ob[4]);
            oa[5] = fma2(ea2, v45.b, oa[5]); ob[5] = fma2(eb2, v45.b, ob[5]);
            oa[6] = fma2(ea2, v67.a, oa[6]); ob[6] = fma2(eb2, v67.a, ob[6]);
            oa[7] = fma2(ea2, v67.b, oa[7]); ob[7] = fma2(eb2, v67.b, ob[7]);
        }
    }

    // --- final reductions ---
#pragma unroll
    for (int off = 16; off; off >>= 1) {
        ssa += __shfl_xor_sync(0xFFFFFFFFu, ssa, off);
        ssb += __shfl_xor_sync(0xFFFFFFFFu, ssb, off);
    }
    const float inva = 1.0f / ssa;
    const float invb = 1.0f / ssb;

    float outa[16], outb[16];
#pragma unroll
    for (int j = 0; j < 8; j++) {
        upk(oa[j], outa[2 * j], outa[2 * j + 1]);
        upk(ob[j], outb[2 * j], outb[2 * j + 1]);
    }
#pragma unroll
    for (int d = 0; d < 16; d++) {
#pragma unroll
        for (int off = 16; off; off >>= 1) {
            outa[d] += __shfl_xor_sync(0xFFFFFFFFu, outa[d], off);
            outb[d] += __shfl_xor_sync(0xFFFFFFFFu, outb[d], off);
        }
    }
    if (lane < 16) {
        Out[((size_t)(b * Rn + ra)) * En + h * Dn + lane] = outa[lane] * inva;
        Out[((size_t)(b * Rn + rb)) * En + h * Dn + lane] = outb[lane] * invb;
    }
}

// ---------------- instance norm: grid (E/16, B), block (16,16) ----------------
__global__ __launch_bounds__(256)
void inorm_kernel(const float* __restrict__ X, const float* __restrict__ gamma,
                  const float* __restrict__ beta, float* __restrict__ Y)
{
    const int b = blockIdx.y;
    const int tx = threadIdx.x;            // e within chunk
    const int ty = threadIdx.y;            // r stride
    const int e = blockIdx.x * 16 + tx;
    const float* xb = X + (size_t)b * Rn * En;
    float* yb = Y + (size_t)b * Rn * En;

    float s = 0.0f, s2 = 0.0f;
    for (int r = ty; r < Rn; r += 16) {
        float v = xb[(size_t)r * En + e];
        s += v; s2 += v * v;
    }
    __shared__ float ss[16][17], sq[16][17];
    __shared__ float sa_[16], sbb[16];
    ss[ty][tx] = s;
    sq[ty][tx] = s2;
    __syncthreads();
    if (ty == 0) {
        float t = 0.0f, t2 = 0.0f;
#pragma unroll
        for (int j = 0; j < 16; j++) { t += ss[j][tx]; t2 += sq[j][tx]; }
        float mean = t * (1.0f / Rn);
        float var  = t2 * (1.0f / Rn) - mean * mean;
        float rstd = rsqrtf(var + 1e-5f);
        float a = gamma[e] * rstd;
        sa_[tx] = a;
        sbb[tx] = beta[e] - mean * a;
    }
    __syncthreads();
    const float a = sa_[tx], bb = sbb[tx];
    for (int r = ty; r < Rn; r += 16)
        yb[(size_t)r * En + e] = fmaf(xb[(size_t)r * En + e], a, bb);
}

// ---------------- launch ----------------
extern "C" void kernel_launch(void* const* d_in, const int* in_sizes, int n_in,
                              void* d_out, int out_size)
{
    const float* row_emb = (const float*)d_in[0];
    const float* col_emb = (const float*)d_in[1];
    const float* cost    = (const float*)d_in[2];
    const float* Wq      = (const float*)d_in[3];
    const float* Wk      = (const float*)d_in[4];
    const float* Wv      = (const float*)d_in[5];
    const float* mix1_w  = (const float*)d_in[6];
    const float* mix1_b  = (const float*)d_in[7];
    const float* mix2_w  = (const float*)d_in[8];
    const float* mix2_b  = (const float*)d_in[9];
    const float* Wc      = (const float*)d_in[10];
    const float* bc      = (const float*)d_in[11];
    const float* W1      = (const float*)d_in[12];
    const float* b1      = (const float*)d_in[13];
    const float* W2      = (const float*)d_in[14];
    const float* b2      = (const float*)d_in[15];
    const float* g1      = (const float*)d_in[16];
    const float* be1     = (const float*)d_in[17];
    const float* g2      = (const float*)d_in[18];
    const float* be2     = (const float*)d_in[19];
    float* out = (float*)d_out;

    float *q, *k, *v, *att, *y, *x, *hh, *z;
    cudaGetSymbolAddress((void**)&q,   g_q);
    cudaGetSymbolAddress((void**)&k,   g_k);
    cudaGetSymbolAddress((void**)&v,   g_v);
    cudaGetSymbolAddress((void**)&att, g_att);
    cudaGetSymbolAddress((void**)&y,   g_y);
    cudaGetSymbolAddress((void**)&x,   g_x);
    cudaGetSymbolAddress((void**)&hh,  g_h);
    cudaGetSymbolAddress((void**)&z,   g_z);

    cudaFuncSetAttribute(attn_kernel, cudaFuncAttributeMaxDynamicSharedMemorySize, ATTN_SMEM);

    const int MR = Bn * Rn;   // 2048

    {   // fused QKV
        dim3 g(En / 64, MR / 64, 3);
        qkv_gemm<<<g, 256>>>(row_emb, col_emb, Wq, Wk, Wv, q, k, v);
    }
    {   // fused attention
        dim3 g(Bn * Hn, Rn / ROWS_PER_BLK);
        attn_kernel<<<g, 256, ATTN_SMEM>>>(q, k, v, cost, mix1_w, mix1_b, mix2_w, mix2_b, att);
    }
    {   // combine + residual
        dim3 g(En / 64, MR / 64);
        gemm64<false, true><<<g, 256>>>(att, Wc, bc, row_emb, y, MR, En, En);
    }
    {   // norm1
        dim3 g(En / 16, Bn);
        inorm_kernel<<<g, dim3(16, 16)>>>(y, g1, be1, x);
    }
    {   // FFN
        dim3 ga(Fn / 64, MR / 64);
        gemm64<true, false><<<ga, 256>>>(x, W1, b1, nullptr, hh, MR, Fn, En);
        dim3 gb(En / 64, MR / 64);
        gemm64<false, true><<<gb, 256>>>(hh, W2, b2, x, z, MR, En, Fn);
    }
    {   // norm2 -> out
        dim3 g(En / 16, Bn);
        inorm_kernel<<<g, dim3(16, 16)>>>(z, g2, be2, out);
    }
}

// round 6
// speedup vs baseline: 2.3867x; 1.1388x over previous
#include <cuda_runtime.h>
#include <math.h>

#define Bn 4
#define Rn 512
#define Cn 512
#define En 256
#define Hn 16
#define Dn 16
#define Mn 16
#define Fn 512

// ---------------- packed f32x2 helpers ----------------
typedef unsigned long long u64;
struct __align__(16) U2 { u64 a, b; };

__device__ __forceinline__ u64 pk(float lo, float hi) {
    u64 r; asm("mov.b64 %0,{%1,%2};" : "=l"(r) : "f"(lo), "f"(hi)); return r;
}
__device__ __forceinline__ void upk(u64 v, float& lo, float& hi) {
    asm("mov.b64 {%0,%1},%2;" : "=f"(lo), "=f"(hi) : "l"(v));
}
__device__ __forceinline__ u64 fma2(u64 a, u64 b, u64 c) {
    u64 d; asm("fma.rn.f32x2 %0,%1,%2,%3;" : "=l"(d) : "l"(a), "l"(b), "l"(c)); return d;
}
__device__ __forceinline__ u64 abs2(u64 x) { return x & 0x7FFFFFFF7FFFFFFFULL; }

// ---------------- scratch ----------------
__device__ float g_q[Bn*Rn*En];
__device__ float g_k[Bn*Cn*En];
__device__ float g_v[Bn*Cn*En];
__device__ float g_att[Bn*Rn*En];
__device__ float g_y[Bn*Rn*En];
__device__ float g_x[Bn*Rn*En];
__device__ float g_h[Bn*Rn*Fn];
__device__ float g_z[Bn*Rn*En];

// ---------------- SGEMM: BM=BN=64, BK=16, 256 thr, double-buffered ----------------
template<bool RELU, bool RES>
__device__ __forceinline__
void gemm_body(const float* __restrict__ A, const float* __restrict__ B,
               const float* __restrict__ bias, const float* __restrict__ res,
               float* __restrict__ C, int M, int N, int K)
{
    __shared__ float As[2][16][64];
    __shared__ float Bs[2][16][64];
    const int tid = threadIdx.x;
    const int tx = tid & 15;
    const int ty = tid >> 4;
    const int m0 = blockIdx.y * 64;
    const int n0 = blockIdx.x * 64;

    const int arow = tid >> 2;
    const int acol = (tid & 3) * 4;
    const int brow = tid >> 4;
    const int bcol = (tid & 15) * 4;

    const float* Aptr = &A[(size_t)(m0 + arow) * K + acol];
    const float* Bptr = &B[(size_t)brow * N + n0 + bcol];

    u64 acc2[4][2] = {};

    // prologue: load k-tile 0 into buffer 0
    {
        float4 av = *reinterpret_cast<const float4*>(Aptr);
        float4 bv = *reinterpret_cast<const float4*>(Bptr);
        As[0][acol + 0][arow] = av.x;
        As[0][acol + 1][arow] = av.y;
        As[0][acol + 2][arow] = av.z;
        As[0][acol + 3][arow] = av.w;
        *reinterpret_cast<float4*>(&Bs[0][brow][bcol]) = bv;
    }
    __syncthreads();

    int buf = 0;
    for (int k0 = 0; k0 < K; k0 += 16) {
        float4 nav, nbv;
        const bool more = (k0 + 16) < K;
        if (more) {
            nav = *reinterpret_cast<const float4*>(Aptr + (k0 + 16));
            nbv = *reinterpret_cast<const float4*>(Bptr + (size_t)(k0 + 16) * N);
        }
#pragma unroll
        for (int k = 0; k < 16; k++) {
            float4 a4 = *reinterpret_cast<const float4*>(&As[buf][k][ty * 4]);
            float4 b4 = *reinterpret_cast<const float4*>(&Bs[buf][k][tx * 4]);
            u64 b01 = pk(b4.x, b4.y);
            u64 b23 = pk(b4.z, b4.w);
            u64 a0 = pk(a4.x, a4.x), a1 = pk(a4.y, a4.y);
            u64 a2 = pk(a4.z, a4.z), a3 = pk(a4.w, a4.w);
            acc2[0][0] = fma2(a0, b01, acc2[0][0]); acc2[0][1] = fma2(a0, b23, acc2[0][1]);
            acc2[1][0] = fma2(a1, b01, acc2[1][0]); acc2[1][1] = fma2(a1, b23, acc2[1][1]);
            acc2[2][0] = fma2(a2, b01, acc2[2][0]); acc2[2][1] = fma2(a2, b23, acc2[2][1]);
            acc2[3][0] = fma2(a3, b01, acc2[3][0]); acc2[3][1] = fma2(a3, b23, acc2[3][1]);
        }
        if (more) {
            __syncthreads();
            int nb = buf ^ 1;
            As[nb][acol + 0][arow] = nav.x;
            As[nb][acol + 1][arow] = nav.y;
            As[nb][acol + 2][arow] = nav.z;
            As[nb][acol + 3][arow] = nav.w;
            *reinterpret_cast<float4*>(&Bs[nb][brow][bcol]) = nbv;
            __syncthreads();
            buf = nb;
        }
    }

#pragma unroll
    for (int i = 0; i < 4; i++) {
        int m = m0 + ty * 4 + i;
        float c0, c1, c2, c3;
        upk(acc2[i][0], c0, c1);
        upk(acc2[i][1], c2, c3);
        float vals[4] = {c0, c1, c2, c3};
#pragma unroll
        for (int j = 0; j < 4; j++) {
            int n = n0 + tx * 4 + j;
            float v = vals[j];
            if (bias) v += bias[n];
            if (RES)  v += res[(size_t)m * N + n];
            if (RELU) v = fmaxf(v, 0.0f);
            C[(size_t)m * N + n] = v;
        }
    }
}

template<bool RELU, bool RES>
__global__ __launch_bounds__(256, 2)
void gemm64(const float* __restrict__ A, const float* __restrict__ B,
            const float* __restrict__ bias, const float* __restrict__ res,
            float* __restrict__ C, int M, int N, int K)
{
    gemm_body<RELU, RES>(A, B, bias, res, C, M, N, K);
}

__global__ __launch_bounds__(256, 2)
void qkv_gemm(const float* __restrict__ row_emb, const float* __restrict__ col_emb,
              const float* __restrict__ Wq, const float* __restrict__ Wk,
              const float* __restrict__ Wv,
              float* __restrict__ q, float* __restrict__ k, float* __restrict__ v)
{
    const float* A; const float* B; float* C;
    if (blockIdx.z == 0)      { A = row_emb; B = Wq; C = q; }
    else if (blockIdx.z == 1) { A = col_emb; B = Wk; C = k; }
    else                      { A = col_emb; B = Wv; C = v; }
    gemm_body<false, false>(A, B, nullptr, nullptr, C, Bn * Rn, En, En);
}

// ---------------- fused attention (non-online softmax, phase-split) ----------------
// grid (B*H, R/16), 256 thr (8 warps). Warp w owns rows (r0+w, r0+w+8) packed
// into f32x2 lanes (lo=rowA, hi=rowB). Phase 1: all 512 scores -> mx2[16].
// Phase 2: global max, exp + PV streaming.
#define KV_STRIDE 20
#define ATTN_SMEM ((Cn * KV_STRIDE * 2 + 16 * Dn) * (int)sizeof(float))
#define ROWS_PER_BLK 16

__global__ __launch_bounds__(256, 2)
void attn_kernel(const float* __restrict__ Q, const float* __restrict__ K,
                 const float* __restrict__ V, const float* __restrict__ cost,
                 const float* __restrict__ mix1_w, const float* __restrict__ mix1_b,
                 const float* __restrict__ mix2_w, const float* __restrict__ mix2_b,
                 float* __restrict__ Out)
{
    extern __shared__ float sh[];
    float* ksh = sh;                        // 512 x 20
    float* vsh = sh + Cn * KV_STRIDE;       // 512 x 20
    float* qsh = vsh + Cn * KV_STRIDE;      // 16 x 16

    __shared__ U2 swA[Mn];    // {wd2, wc2}
    __shared__ U2 swB[Mn];    // {wb2, w2h2}  (w2h = w2/2)
    __shared__ float sb2;

    const int tid = threadIdx.x;
    const int b = blockIdx.x >> 4;
    const int h = blockIdx.x & 15;
    const int r0 = blockIdx.y * ROWS_PER_BLK;

    if (tid < Mn) {
        float wd = mix1_w[h * 2 * Mn + tid];
        float wc = mix1_w[h * 2 * Mn + Mn + tid];
        float wb = mix1_b[h * Mn + tid];
        float w2h = 0.5f * mix2_w[h * Mn + tid];
        swA[tid].a = pk(wd, wd);
        swA[tid].b = pk(wc, wc);
        swB[tid].a = pk(wb, wb);
        swB[tid].b = pk(w2h, w2h);
    }
    if (tid == 0) sb2 = mix2_b[h];

    for (int idx = tid; idx < Cn * 4; idx += 256) {
        int c = idx >> 2, g = idx & 3;
        size_t src = ((size_t)(b * Cn + c)) * En + h * Dn + g * 4;
        *reinterpret_cast<float4*>(&ksh[c * KV_STRIDE + g * 4]) =
            *reinterpret_cast<const float4*>(&K[src]);
        *reinterpret_cast<float4*>(&vsh[c * KV_STRIDE + g * 4]) =
            *reinterpret_cast<const float4*>(&V[src]);
    }
    if (tid < ROWS_PER_BLK * Dn) {
        int rr = tid >> 4, d = tid & 15;
        qsh[tid] = Q[((size_t)(b * Rn + r0 + rr)) * En + h * Dn + d];
    }
    __syncthreads();

    const int warp = tid >> 5;
    const int lane = tid & 31;
    const int ra = r0 + warp;
    const int rb = r0 + warp + 8;

    const float* crA = &cost[((size_t)(b * Rn + ra)) * Cn];
    const float* crB = &cost[((size_t)(b * Rn + rb)) * Cn];
    const u64 binit = pk(sb2, sb2);

    u64 mx2[16];

    // ---------------- phase 1: scores + mix MLP ----------------
#pragma unroll
    for (int st = 0; st < 2; st++) {
        u64 dot2[8], cv2[8];
        {
            // Q rows packed per d-pair (reload per chunk to keep them short-lived)
            const u64* pa = reinterpret_cast<const u64*>(&qsh[warp * Dn]);
            const u64* pb = reinterpret_cast<const u64*>(&qsh[(warp + 8) * Dn]);
            u64 qa[8], qb[8];
#pragma unroll
            for (int j = 0; j < 8; j++) { qa[j] = pa[j]; qb[j] = pb[j]; }
#pragma unroll
            for (int i = 0; i < 8; i++) {
                int c = lane + 32 * (st * 8 + i);
                const U2* kp = reinterpret_cast<const U2*>(&ksh[c * KV_STRIDE]);
                U2 k01 = kp[0], k23 = kp[1], k45 = kp[2], k67 = kp[3];
                u64 aA = 0, aB = 0;
                aA = fma2(qa[0], k01.a, aA); aB = fma2(qb[0], k01.a, aB);
                aA = fma2(qa[1], k01.b, aA); aB = fma2(qb[1], k01.b, aB);
                aA = fma2(qa[2], k23.a, aA); aB = fma2(qb[2], k23.a, aB);
                aA = fma2(qa[3], k23.b, aA); aB = fma2(qb[3], k23.b, aB);
                aA = fma2(qa[4], k45.a, aA); aB = fma2(qb[4], k45.a, aB);
                aA = fma2(qa[5], k45.b, aA); aB = fma2(qb[5], k45.b, aB);
                aA = fma2(qa[6], k67.a, aA); aB = fma2(qb[6], k67.a, aB);
                aA = fma2(qa[7], k67.b, aA); aB = fma2(qb[7], k67.b, aB);
                float x0, x1, y0, y1;
                upk(aA, x0, x1); upk(aB, y0, y1);
                dot2[i] = pk((x0 + x1) * 0.25f, (y0 + y1) * 0.25f);
                cv2[i]  = pk(__ldg(&crA[c]), __ldg(&crB[c]));
                mx2[st * 8 + i] = binit;
            }
        }
        // mix MLP: w2*relu(t) == w2h*t + w2h*|t|
#pragma unroll
        for (int m = 0; m < Mn; m++) {
            U2 w1 = swA[m];
            U2 w2 = swB[m];
#pragma unroll
            for (int i = 0; i < 8; i++) {
                u64 t = fma2(dot2[i], w1.a, fma2(cv2[i], w1.b, w2.a));
                mx2[st * 8 + i] = fma2(abs2(t), w2.b, fma2(t, w2.b, mx2[st * 8 + i]));
            }
        }
    }

    // ---------------- phase 2: softmax + PV ----------------
    float Ma = -1e30f, Mb = -1e30f;
#pragma unroll
    for (int i = 0; i < 16; i++) {
        float xa, xb; upk(mx2[i], xa, xb);
        Ma = fmaxf(Ma, xa); Mb = fmaxf(Mb, xb);
    }
#pragma unroll
    for (int off = 16; off; off >>= 1) {
        Ma = fmaxf(Ma, __shfl_xor_sync(0xFFFFFFFFu, Ma, off));
        Mb = fmaxf(Mb, __shfl_xor_sync(0xFFFFFFFFu, Mb, off));
    }

    u64 oa[8] = {}, ob[8] = {};
    float ssa = 0.0f, ssb = 0.0f;
#pragma unroll
    for (int i = 0; i < 16; i++) {
        int c = lane + 32 * i;
        float xa, xb; upk(mx2[i], xa, xb);
        float ea = __expf(xa - Ma);
        float eb = __expf(xb - Mb);
        ssa += ea; ssb += eb;
        const U2* vp = reinterpret_cast<const U2*>(&vsh[c * KV_STRIDE]);
        U2 v01 = vp[0], v23 = vp[1], v45 = vp[2], v67 = vp[3];
        u64 ea2 = pk(ea, ea), eb2 = pk(eb, eb);
        oa[0] = fma2(ea2, v01.a, oa[0]); ob[0] = fma2(eb2, v01.a, ob[0]);
        oa[1] = fma2(ea2, v01.b, oa[1]); ob[1] = fma2(eb2, v01.b, ob[1]);
        oa[2] = fma2(ea2, v23.a, oa[2]); ob[2] = fma2(eb2, v23.a, ob[2]);
        oa[3] = fma2(ea2, v23.b, oa[3]); ob[3] = fma2(eb2, v23.b, ob[3]);
        oa[4] = fma2(ea2, v45.a, oa[4]); ob[4] = fma2(eb2, v45.a, ob[4]);
        oa[5] = fma2(ea2, v45.b, oa[5]); ob[5] = fma2(eb2, v45.b, ob[5]);
        oa[6] = fma2(ea2, v67.a, oa[6]); ob[6] = fma2(eb2, v67.a, ob[6]);
        oa[7] = fma2(ea2, v67.b, oa[7]); ob[7] = fma2(eb2, v67.b, ob[7]);
    }

#pragma unroll
    for (int off = 16; off; off >>= 1) {
        ssa += __shfl_xor_sync(0xFFFFFFFFu, ssa, off);
        ssb += __shfl_xor_sync(0xFFFFFFFFu, ssb, off);
    }
    const float inva = 1.0f / ssa;
    const float invb = 1.0f / ssb;

    float outa[16], outb[16];
#pragma unroll
    for (int j = 0; j < 8; j++) {
        upk(oa[j], outa[2 * j], outa[2 * j + 1]);
        upk(ob[j], outb[2 * j], outb[2 * j + 1]);
    }
#pragma unroll
    for (int d = 0; d < 16; d++) {
#pragma unroll
        for (int off = 16; off; off >>= 1) {
            outa[d] += __shfl_xor_sync(0xFFFFFFFFu, outa[d], off);
            outb[d] += __shfl_xor_sync(0xFFFFFFFFu, outb[d], off);
        }
    }
    if (lane < 16) {
        Out[((size_t)(b * Rn + ra)) * En + h * Dn + lane] = outa[lane] * inva;
        Out[((size_t)(b * Rn + rb)) * En + h * Dn + lane] = outb[lane] * invb;
    }
}

// ---------------- instance norm: grid (E/16, B), block (16,16) ----------------
__global__ __launch_bounds__(256)
void inorm_kernel(const float* __restrict__ X, const float* __restrict__ gamma,
                  const float* __restrict__ beta, float* __restrict__ Y)
{
    const int b = blockIdx.y;
    const int tx = threadIdx.x;
    const int ty = threadIdx.y;
    const int e = blockIdx.x * 16 + tx;
    const float* xb = X + (size_t)b * Rn * En;
    float* yb = Y + (size_t)b * Rn * En;

    float s = 0.0f, s2 = 0.0f;
    for (int r = ty; r < Rn; r += 16) {
        float v = xb[(size_t)r * En + e];
        s += v; s2 += v * v;
    }
    __shared__ float ss[16][17], sq[16][17];
    __shared__ float sa_[16], sbb[16];
    ss[ty][tx] = s;
    sq[ty][tx] = s2;
    __syncthreads();
    if (ty == 0) {
        float t = 0.0f, t2 = 0.0f;
#pragma unroll
        for (int j = 0; j < 16; j++) { t += ss[j][tx]; t2 += sq[j][tx]; }
        float mean = t * (1.0f / Rn);
        float var  = t2 * (1.0f / Rn) - mean * mean;
        float rstd = rsqrtf(var + 1e-5f);
        float a = gamma[e] * rstd;
        sa_[tx] = a;
        sbb[tx] = beta[e] - mean * a;
    }
    __syncthreads();
    const float a = sa_[tx], bb = sbb[tx];
    for (int r = ty; r < Rn; r += 16)
        yb[(size_t)r * En + e] = fmaf(xb[(size_t)r * En + e], a, bb);
}

// ---------------- launch ----------------
extern "C" void kernel_launch(void* const* d_in, const int* in_sizes, int n_in,
                              void* d_out, int out_size)
{
    const float* row_emb = (const float*)d_in[0];
    const float* col_emb = (const float*)d_in[1];
    const float* cost    = (const float*)d_in[2];
    const float* Wq      = (const float*)d_in[3];
    const float* Wk      = (const float*)d_in[4];
    const float* Wv      = (const float*)d_in[5];
    const float* mix1_w  = (const float*)d_in[6];
    const float* mix1_b  = (const float*)d_in[7];
    const float* mix2_w  = (const float*)d_in[8];
    const float* mix2_b  = (const float*)d_in[9];
    const float* Wc      = (const float*)d_in[10];
    const float* bc      = (const float*)d_in[11];
    const float* W1      = (const float*)d_in[12];
    const float* b1      = (const float*)d_in[13];
    const float* W2      = (const float*)d_in[14];
    const float* b2      = (const float*)d_in[15];
    const float* g1      = (const float*)d_in[16];
    const float* be1     = (const float*)d_in[17];
    const float* g2      = (const float*)d_in[18];
    const float* be2     = (const float*)d_in[19];
    float* out = (float*)d_out;

    float *q, *k, *v, *att, *y, *x, *hh, *z;
    cudaGetSymbolAddress((void**)&q,   g_q);
    cudaGetSymbolAddress((void**)&k,   g_k);
    cudaGetSymbolAddress((void**)&v,   g_v);
    cudaGetSymbolAddress((void**)&att, g_att);
    cudaGetSymbolAddress((void**)&y,   g_y);
    cudaGetSymbolAddress((void**)&x,   g_x);
    cudaGetSymbolAddress((void**)&hh,  g_h);
    cudaGetSymbolAddress((void**)&z,   g_z);

    cudaFuncSetAttribute(attn_kernel, cudaFuncAttributeMaxDynamicSharedMemorySize, ATTN_SMEM);

    const int MR = Bn * Rn;   // 2048

    {   // fused QKV
        dim3 g(En / 64, MR / 64, 3);
        qkv_gemm<<<g, 256>>>(row_emb, col_emb, Wq, Wk, Wv, q, k, v);
    }
    {   // fused attention
        dim3 g(Bn * Hn, Rn / ROWS_PER_BLK);
        attn_kernel<<<g, 256, ATTN_SMEM>>>(q, k, v, cost, mix1_w, mix1_b, mix2_w, mix2_b, att);
    }
    {   // combine + residual
        dim3 g(En / 64, MR / 64);
        gemm64<false, true><<<g, 256>>>(att, Wc, bc, row_emb, y, MR, En, En);
    }
    {   // norm1
        dim3 g(En / 16, Bn);
        inorm_kernel<<<g, dim3(16, 16)>>>(y, g1, be1, x);
    }
    {   // FFN
        dim3 ga(Fn / 64, MR / 64);
        gemm64<true, false><<<ga, 256>>>(x, W1, b1, nullptr, hh, MR, Fn, En);
        dim3 gb(En / 64, MR / 64);
        gemm64<false, true><<<gb, 256>>>(hh, W2, b2, x, z, MR, En, Fn);
    }
    {   // norm2 -> out
        dim3 g(En / 16, Bn);
        inorm_kernel<<<g, dim3(16, 16)>>>(z, g2, be2, out);
    }
}

// round 7
// speedup vs baseline: 2.6025x; 1.0904x over previous
#include <cuda_runtime.h>
#include <math.h>

#define Bn 4
#define Rn 512
#define Cn 512
#define En 256
#define Hn 16
#define Dn 16
#define Mn 16
#define Fn 512

// ---------------- packed f32x2 helpers ----------------
typedef unsigned long long u64;
struct __align__(16) U2 { u64 a, b; };

__device__ __forceinline__ u64 pk(float lo, float hi) {
    u64 r; asm("mov.b64 %0,{%1,%2};" : "=l"(r) : "f"(lo), "f"(hi)); return r;
}
__device__ __forceinline__ void upk(u64 v, float& lo, float& hi) {
    asm("mov.b64 {%0,%1},%2;" : "=f"(lo), "=f"(hi) : "l"(v));
}
__device__ __forceinline__ u64 fma2(u64 a, u64 b, u64 c) {
    u64 d; asm("fma.rn.f32x2 %0,%1,%2,%3;" : "=l"(d) : "l"(a), "l"(b), "l"(c)); return d;
}
__device__ __forceinline__ u64 add2(u64 a, u64 b) {
    u64 d; asm("add.rn.f32x2 %0,%1,%2;" : "=l"(d) : "l"(a), "l"(b)); return d;
}
__device__ __forceinline__ u64 abs2(u64 x) { return x & 0x7FFFFFFF7FFFFFFFULL; }
__device__ __forceinline__ u64 shflx2(u64 v, int m) {
    float lo, hi; upk(v, lo, hi);
    lo = __shfl_xor_sync(0xFFFFFFFFu, lo, m);
    hi = __shfl_xor_sync(0xFFFFFFFFu, hi, m);
    return pk(lo, hi);
}

// ---------------- scratch ----------------
__device__ float g_q[Bn*Rn*En];
__device__ float g_k[Bn*Cn*En];
__device__ float g_v[Bn*Cn*En];
__device__ float g_att[Bn*Rn*En];
__device__ float g_y[Bn*Rn*En];
__device__ float g_x[Bn*Rn*En];
__device__ float g_h[Bn*Rn*Fn];
__device__ float g_z[Bn*Rn*En];

// ---------------- SGEMM: BM=BN=64, BK=16, 256 thr, double-buffered ----------------
template<bool RELU, bool RES>
__device__ __forceinline__
void gemm_body(const float* __restrict__ A, const float* __restrict__ B,
               const float* __restrict__ bias, const float* __restrict__ res,
               float* __restrict__ C, int M, int N, int K)
{
    __shared__ float As[2][16][64];
    __shared__ float Bs[2][16][64];
    const int tid = threadIdx.x;
    const int tx = tid & 15;
    const int ty = tid >> 4;
    const int m0 = blockIdx.y * 64;
    const int n0 = blockIdx.x * 64;

    const int arow = tid >> 2;
    const int acol = (tid & 3) * 4;
    const int brow = tid >> 4;
    const int bcol = (tid & 15) * 4;

    const float* Aptr = &A[(size_t)(m0 + arow) * K + acol];
    const float* Bptr = &B[(size_t)brow * N + n0 + bcol];

    u64 acc2[4][2] = {};

    {
        float4 av = *reinterpret_cast<const float4*>(Aptr);
        float4 bv = *reinterpret_cast<const float4*>(Bptr);
        As[0][acol + 0][arow] = av.x;
        As[0][acol + 1][arow] = av.y;
        As[0][acol + 2][arow] = av.z;
        As[0][acol + 3][arow] = av.w;
        *reinterpret_cast<float4*>(&Bs[0][brow][bcol]) = bv;
    }
    __syncthreads();

    int buf = 0;
    for (int k0 = 0; k0 < K; k0 += 16) {
        float4 nav, nbv;
        const bool more = (k0 + 16) < K;
        if (more) {
            nav = *reinterpret_cast<const float4*>(Aptr + (k0 + 16));
            nbv = *reinterpret_cast<const float4*>(Bptr + (size_t)(k0 + 16) * N);
        }
#pragma unroll
        for (int k = 0; k < 16; k++) {
            float4 a4 = *reinterpret_cast<const float4*>(&As[buf][k][ty * 4]);
            float4 b4 = *reinterpret_cast<const float4*>(&Bs[buf][k][tx * 4]);
            u64 b01 = pk(b4.x, b4.y);
            u64 b23 = pk(b4.z, b4.w);
            u64 a0 = pk(a4.x, a4.x), a1 = pk(a4.y, a4.y);
            u64 a2 = pk(a4.z, a4.z), a3 = pk(a4.w, a4.w);
            acc2[0][0] = fma2(a0, b01, acc2[0][0]); acc2[0][1] = fma2(a0, b23, acc2[0][1]);
            acc2[1][0] = fma2(a1, b01, acc2[1][0]); acc2[1][1] = fma2(a1, b23, acc2[1][1]);
            acc2[2][0] = fma2(a2, b01, acc2[2][0]); acc2[2][1] = fma2(a2, b23, acc2[2][1]);
            acc2[3][0] = fma2(a3, b01, acc2[3][0]); acc2[3][1] = fma2(a3, b23, acc2[3][1]);
        }
        if (more) {
            __syncthreads();
            int nb = buf ^ 1;
            As[nb][acol + 0][arow] = nav.x;
            As[nb][acol + 1][arow] = nav.y;
            As[nb][acol + 2][arow] = nav.z;
            As[nb][acol + 3][arow] = nav.w;
            *reinterpret_cast<float4*>(&Bs[nb][brow][bcol]) = nbv;
            __syncthreads();
            buf = nb;
        }
    }

#pragma unroll
    for (int i = 0; i < 4; i++) {
        int m = m0 + ty * 4 + i;
        float c0, c1, c2, c3;
        upk(acc2[i][0], c0, c1);
        upk(acc2[i][1], c2, c3);
        float vals[4] = {c0, c1, c2, c3};
#pragma unroll
        for (int j = 0; j < 4; j++) {
            int n = n0 + tx * 4 + j;
            float v = vals[j];
            if (bias) v += bias[n];
            if (RES)  v += res[(size_t)m * N + n];
            if (RELU) v = fmaxf(v, 0.0f);
            C[(size_t)m * N + n] = v;
        }
    }
}

template<bool RELU, bool RES>
__global__ __launch_bounds__(256, 2)
void gemm64(const float* __restrict__ A, const float* __restrict__ B,
            const float* __restrict__ bias, const float* __restrict__ res,
            float* __restrict__ C, int M, int N, int K)
{
    gemm_body<RELU, RES>(A, B, bias, res, C, M, N, K);
}

__global__ __launch_bounds__(256, 2)
void qkv_gemm(const float* __restrict__ row_emb, const float* __restrict__ col_emb,
              const float* __restrict__ Wq, const float* __restrict__ Wk,
              const float* __restrict__ Wv,
              float* __restrict__ q, float* __restrict__ k, float* __restrict__ v)
{
    const float* A; const float* B; float* C;
    if (blockIdx.z == 0)      { A = row_emb; B = Wq; C = q; }
    else if (blockIdx.z == 1) { A = col_emb; B = Wk; C = k; }
    else                      { A = col_emb; B = Wv; C = v; }
    gemm_body<false, false>(A, B, nullptr, nullptr, C, Bn * Rn, En, En);
}

// ---------------- fused attention ----------------
// grid (B*H, R/32), 256 thr (8 warps). Each warp handles 2 sequential groups
// of 2 rows (rows packed into f32x2 lanes). K/V smem fill amortized over 32 rows.
#define KV_STRIDE 20
#define ROWS_PER_BLK 32
#define ATTN_SMEM ((Cn * KV_STRIDE * 2 + ROWS_PER_BLK * Dn) * (int)sizeof(float))

__global__ __launch_bounds__(256, 2)
void attn_kernel(const float* __restrict__ Q, const float* __restrict__ K,
                 const float* __restrict__ V, const float* __restrict__ cost,
                 const float* __restrict__ mix1_w, const float* __restrict__ mix1_b,
                 const float* __restrict__ mix2_w, const float* __restrict__ mix2_b,
                 float* __restrict__ Out)
{
    extern __shared__ float sh[];
    float* ksh = sh;                        // 512 x 20
    float* vsh = sh + Cn * KV_STRIDE;       // 512 x 20
    float* qsh = vsh + Cn * KV_STRIDE;      // 32 x 16

    __shared__ U2 swA[Mn];    // {wd2, wc2}
    __shared__ U2 swB[Mn];    // {wb2, w2h2}  (w2h = w2/2)
    __shared__ float sb2;

    const int tid = threadIdx.x;
    const int b = blockIdx.x >> 4;
    const int h = blockIdx.x & 15;
    const int r0 = blockIdx.y * ROWS_PER_BLK;

    if (tid < Mn) {
        float wd = mix1_w[h * 2 * Mn + tid];
        float wc = mix1_w[h * 2 * Mn + Mn + tid];
        float wb = mix1_b[h * Mn + tid];
        float w2h = 0.5f * mix2_w[h * Mn + tid];
        swA[tid].a = pk(wd, wd);
        swA[tid].b = pk(wc, wc);
        swB[tid].a = pk(wb, wb);
        swB[tid].b = pk(w2h, w2h);
    }
    if (tid == 0) sb2 = mix2_b[h];

    for (int idx = tid; idx < Cn * 4; idx += 256) {
        int c = idx >> 2, g = idx & 3;
        size_t src = ((size_t)(b * Cn + c)) * En + h * Dn + g * 4;
        *reinterpret_cast<float4*>(&ksh[c * KV_STRIDE + g * 4]) =
            *reinterpret_cast<const float4*>(&K[src]);
        *reinterpret_cast<float4*>(&vsh[c * KV_STRIDE + g * 4]) =
            *reinterpret_cast<const float4*>(&V[src]);
    }
    for (int idx = tid; idx < ROWS_PER_BLK * Dn; idx += 256) {
        int rr = idx >> 4, d = idx & 15;
        qsh[idx] = Q[((size_t)(b * Rn + r0 + rr)) * En + h * Dn + d];
    }
    __syncthreads();

    const int warp = tid >> 5;
    const int lane = tid & 31;
    const u64 binit = pk(sb2, sb2);

#pragma unroll 1
    for (int grp = 0; grp < 2; grp++) {
        const int ra = r0 + grp * 16 + warp;
        const int rb = ra + 8;
        const int qoff = grp * 16 + warp;

        const float* crA = &cost[((size_t)(b * Rn + ra)) * Cn];
        const float* crB = &cost[((size_t)(b * Rn + rb)) * Cn];

        u64 mx2[16];

        // ---------------- phase 1: scores + mix MLP ----------------
#pragma unroll
        for (int st = 0; st < 2; st++) {
            u64 dot2[8], cv2[8];
            {
                const u64* pa = reinterpret_cast<const u64*>(&qsh[qoff * Dn]);
                const u64* pb = reinterpret_cast<const u64*>(&qsh[(qoff + 8) * Dn]);
                u64 qa[8], qb[8];
#pragma unroll
                for (int j = 0; j < 8; j++) { qa[j] = pa[j]; qb[j] = pb[j]; }
#pragma unroll
                for (int i = 0; i < 8; i++) {
                    int c = lane + 32 * (st * 8 + i);
                    const U2* kp = reinterpret_cast<const U2*>(&ksh[c * KV_STRIDE]);
                    U2 k01 = kp[0], k23 = kp[1], k45 = kp[2], k67 = kp[3];
                    u64 aA = 0, aB = 0;
                    aA = fma2(qa[0], k01.a, aA); aB = fma2(qb[0], k01.a, aB);
                    aA = fma2(qa[1], k01.b, aA); aB = fma2(qb[1], k01.b, aB);
                    aA = fma2(qa[2], k23.a, aA); aB = fma2(qb[2], k23.a, aB);
                    aA = fma2(qa[3], k23.b, aA); aB = fma2(qb[3], k23.b, aB);
                    aA = fma2(qa[4], k45.a, aA); aB = fma2(qb[4], k45.a, aB);
                    aA = fma2(qa[5], k45.b, aA); aB = fma2(qb[5], k45.b, aB);
                    aA = fma2(qa[6], k67.a, aA); aB = fma2(qb[6], k67.a, aB);
                    aA = fma2(qa[7], k67.b, aA); aB = fma2(qb[7], k67.b, aB);
                    float x0, x1, y0, y1;
                    upk(aA, x0, x1); upk(aB, y0, y1);
                    dot2[i] = pk((x0 + x1) * 0.25f, (y0 + y1) * 0.25f);
                    cv2[i]  = pk(__ldg(&crA[c]), __ldg(&crB[c]));
                    mx2[st * 8 + i] = binit;
                }
            }
            // mix MLP: w2*relu(t) == w2h*t + w2h*|t|
#pragma unroll
            for (int m = 0; m < Mn; m++) {
                U2 w1 = swA[m];
                U2 w2 = swB[m];
#pragma unroll
                for (int i = 0; i < 8; i++) {
                    u64 t = fma2(dot2[i], w1.a, fma2(cv2[i], w1.b, w2.a));
                    mx2[st * 8 + i] = fma2(abs2(t), w2.b, fma2(t, w2.b, mx2[st * 8 + i]));
                }
            }
        }

        // ---------------- phase 2: softmax + PV ----------------
        float Ma = -1e30f, Mb = -1e30f;
#pragma unroll
        for (int i = 0; i < 16; i++) {
            float xa, xb; upk(mx2[i], xa, xb);
            Ma = fmaxf(Ma, xa); Mb = fmaxf(Mb, xb);
        }
#pragma unroll
        for (int off = 16; off; off >>= 1) {
            Ma = fmaxf(Ma, __shfl_xor_sync(0xFFFFFFFFu, Ma, off));
            Mb = fmaxf(Mb, __shfl_xor_sync(0xFFFFFFFFu, Mb, off));
        }

        u64 oa[8] = {}, ob[8] = {};
        float ssa = 0.0f, ssb = 0.0f;
#pragma unroll
        for (int i = 0; i < 16; i++) {
            int c = lane + 32 * i;
            float xa, xb; upk(mx2[i], xa, xb);
            float ea = __expf(xa - Ma);
            float eb = __expf(xb - Mb);
            ssa += ea; ssb += eb;
            const U2* vp = reinterpret_cast<const U2*>(&vsh[c * KV_STRIDE]);
            U2 v01 = vp[0], v23 = vp[1], v45 = vp[2], v67 = vp[3];
            u64 ea2 = pk(ea, ea), eb2 = pk(eb, eb);
            oa[0] = fma2(ea2, v01.a, oa[0]); ob[0] = fma2(eb2, v01.a, ob[0]);
            oa[1] = fma2(ea2, v01.b, oa[1]); ob[1] = fma2(eb2, v01.b, ob[1]);
            oa[2] = fma2(ea2, v23.a, oa[2]); ob[2] = fma2(eb2, v23.a, ob[2]);
            oa[3] = fma2(ea2, v23.b, oa[3]); ob[3] = fma2(eb2, v23.b, ob[3]);
            oa[4] = fma2(ea2, v45.a, oa[4]); ob[4] = fma2(eb2, v45.a, ob[4]);
            oa[5] = fma2(ea2, v45.b, oa[5]); ob[5] = fma2(eb2, v45.b, ob[5]);
            oa[6] = fma2(ea2, v67.a, oa[6]); ob[6] = fma2(eb2, v67.a, ob[6]);
            oa[7] = fma2(ea2, v67.b, oa[7]); ob[7] = fma2(eb2, v67.b, ob[7]);
        }

#pragma unroll
        for (int off = 16; off; off >>= 1) {
            ssa += __shfl_xor_sync(0xFFFFFFFFu, ssa, off);
            ssb += __shfl_xor_sync(0xFFFFFFFFu, ssb, off);
        }
        const float inva = 1.0f / ssa;
        const float invb = 1.0f / ssb;

        // ---- recursive-halving reduction: lane ends with (row=lane>=16, d=lane&15) ----
        const bool hi16 = (lane & 16) != 0;
        u64 k8[8];
#pragma unroll
        for (int j = 0; j < 8; j++) {
            u64 kp_ = hi16 ? ob[j] : oa[j];
            u64 sd  = hi16 ? oa[j] : ob[j];
            k8[j] = add2(kp_, shflx2(sd, 16));
        }
        const bool hb8 = (lane & 8) != 0;
        u64 k4[4];
#pragma unroll
        for (int j = 0; j < 4; j++) {
            u64 kp_ = hb8 ? k8[j + 4] : k8[j];
            u64 sd  = hb8 ? k8[j] : k8[j + 4];
            k4[j] = add2(kp_, shflx2(sd, 8));
        }
        const bool hb4 = (lane & 4) != 0;
        u64 k2[2];
#pragma unroll
        for (int j = 0; j < 2; j++) {
            u64 kp_ = hb4 ? k4[j + 2] : k4[j];
            u64 sd  = hb4 ? k4[j] : k4[j + 2];
            k2[j] = add2(kp_, shflx2(sd, 4));
        }
        const bool hb2 = (lane & 2) != 0;
        u64 k1 = add2(hb2 ? k2[1] : k2[0], shflx2(hb2 ? k2[0] : k2[1], 2));
        float lo, hi; upk(k1, lo, hi);
        float kf = (lane & 1) ? hi : lo;
        float sf = (lane & 1) ? lo : hi;
        float val = kf + __shfl_xor_sync(0xFFFFFFFFu, sf, 1);

        const float invv = hi16 ? invb : inva;
        const int  rw   = hi16 ? rb : ra;
        Out[((size_t)(b * Rn + rw)) * En + h * Dn + (lane & 15)] = val * invv;
    }
}

// ---------------- instance norm: grid (E/8, B), 256 thr, float4 ----------------
// Each block: 8 e-columns (2 float4) of one batch. tid -> (e4sub = tid&1, rgrp = tid>>1).
__global__ __launch_bounds__(256)
void inorm_kernel(const float* __restrict__ X, const float* __restrict__ gamma,
                  const float* __restrict__ beta, float* __restrict__ Y)
{
    const int b = blockIdx.y;
    const int tid = threadIdx.x;
    const int es = tid & 1;                 // which float4 (of 2)
    const int rg = tid >> 1;                // 0..127
    const int e4 = blockIdx.x * 2 + es;     // float4 column index (E/4 = 64 total)
    const float4* xb = reinterpret_cast<const float4*>(X + (size_t)b * Rn * En);
    float4* yb = reinterpret_cast<float4*>(Y + (size_t)b * Rn * En);
    const int s4 = En / 4;                  // 64

    float4 s = {0,0,0,0}, s2 = {0,0,0,0};
    for (int r = rg; r < Rn; r += 128) {
        float4 v = xb[(size_t)r * s4 + e4];
        s.x += v.x; s.y += v.y; s.z += v.z; s.w += v.w;
        s2.x += v.x*v.x; s2.y += v.y*v.y; s2.z += v.z*v.z; s2.w += v.w*v.w;
    }
    __shared__ float4 ss[128][2], sq[128][2];
    __shared__ float4 sa4[2], sc4[2];
    ss[rg][es] = s;
    sq[rg][es] = s2;
    __syncthreads();
#pragma unroll
    for (int st = 64; st >= 1; st >>= 1) {
        if (rg < st) {
            float4 a = ss[rg][es], c = ss[rg + st][es];
            a.x += c.x; a.y += c.y; a.z += c.z; a.w += c.w;
            ss[rg][es] = a;
            float4 a2 = sq[rg][es], c2 = sq[rg + st][es];
            a2.x += c2.x; a2.y += c2.y; a2.z += c2.z; a2.w += c2.w;
            sq[rg][es] = a2;
        }
        __syncthreads();
    }
    if (tid < 2) {
        float4 t = ss[0][tid], t2 = sq[0][tid];
        float4 gm = reinterpret_cast<const float4*>(gamma)[blockIdx.x * 2 + tid];
        float4 bt = reinterpret_cast<const float4*>(beta)[blockIdx.x * 2 + tid];
        float4 a, c;
        {
            float mean = t.x * (1.0f / Rn);
            float var = t2.x * (1.0f / Rn) - mean * mean;
            float rs = rsqrtf(var + 1e-5f);
            a.x = gm.x * rs; c.x = bt.x - mean * a.x;
            mean = t.y * (1.0f / Rn); var = t2.y * (1.0f / Rn) - mean * mean;
            rs = rsqrtf(var + 1e-5f);
            a.y = gm.y * rs; c.y = bt.y - mean * a.y;
            mean = t.z * (1.0f / Rn); var = t2.z * (1.0f / Rn) - mean * mean;
            rs = rsqrtf(var + 1e-5f);
            a.z = gm.z * rs; c.z = bt.z - mean * a.z;
            mean = t.w * (1.0f / Rn); var = t2.w * (1.0f / Rn) - mean * mean;
            rs = rsqrtf(var + 1e-5f);
            a.w = gm.w * rs; c.w = bt.w - mean * a.w;
        }
        sa4[tid] = a; sc4[tid] = c;
    }
    __syncthreads();
    const float4 a = sa4[es], c = sc4[es];
    for (int r = rg; r < Rn; r += 128) {
        float4 v = xb[(size_t)r * s4 + e4];
        float4 o;
        o.x = fmaf(v.x, a.x, c.x);
        o.y = fmaf(v.y, a.y, c.y);
        o.z = fmaf(v.z, a.z, c.z);
        o.w = fmaf(v.w, a.w, c.w);
        yb[(size_t)r * s4 + e4] = o;
    }
}

// ---------------- launch ----------------
extern "C" void kernel_launch(void* const* d_in, const int* in_sizes, int n_in,
                              void* d_out, int out_size)
{
    const float* row_emb = (const float*)d_in[0];
    const float* col_emb = (const float*)d_in[1];
    const float* cost    = (const float*)d_in[2];
    const float* Wq      = (const float*)d_in[3];
    const float* Wk      = (const float*)d_in[4];
    const float* Wv      = (const float*)d_in[5];
    const float* mix1_w  = (const float*)d_in[6];
    const float* mix1_b  = (const float*)d_in[7];
    const float* mix2_w  = (const float*)d_in[8];
    const float* mix2_b  = (const float*)d_in[9];
    const float* Wc      = (const float*)d_in[10];
    const float* bc      = (const float*)d_in[11];
    const float* W1      = (const float*)d_in[12];
    const float* b1      = (const float*)d_in[13];
    const float* W2      = (const float*)d_in[14];
    const float* b2      = (const float*)d_in[15];
    const float* g1      = (const float*)d_in[16];
    const float* be1     = (const float*)d_in[17];
    const float* g2      = (const float*)d_in[18];
    const float* be2     = (const float*)d_in[19];
    float* out = (float*)d_out;

    float *q, *k, *v, *att, *y, *x, *hh, *z;
    cudaGetSymbolAddress((void**)&q,   g_q);
    cudaGetSymbolAddress((void**)&k,   g_k);
    cudaGetSymbolAddress((void**)&v,   g_v);
    cudaGetSymbolAddress((void**)&att, g_att);
    cudaGetSymbolAddress((void**)&y,   g_y);
    cudaGetSymbolAddress((void**)&x,   g_x);
    cudaGetSymbolAddress((void**)&hh,  g_h);
    cudaGetSymbolAddress((void**)&z,   g_z);

    cudaFuncSetAttribute(attn_kernel, cudaFuncAttributeMaxDynamicSharedMemorySize, ATTN_SMEM);

    const int MR = Bn * Rn;   // 2048

    {   // fused QKV
        dim3 g(En / 64, MR / 64, 3);
        qkv_gemm<<<g, 256>>>(row_emb, col_emb, Wq, Wk, Wv, q, k, v);
    }
    {   // fused attention
        dim3 g(Bn * Hn, Rn / ROWS_PER_BLK);
        attn_kernel<<<g, 256, ATTN_SMEM>>>(q, k, v, cost, mix1_w, mix1_b, mix2_w, mix2_b, att);
    }
    {   // combine + residual
        dim3 g(En / 64, MR / 64);
        gemm64<false, true><<<g, 256>>>(att, Wc, bc, row_emb, y, MR, En, En);
    }
    {   // norm1
        dim3 g(En / 8, Bn);
        inorm_kernel<<<g, 256>>>(y, g1, be1, x);
    }
    {   // FFN
        dim3 ga(Fn / 64, MR / 64);
        gemm64<true, false><<<ga, 256>>>(x, W1, b1, nullptr, hh, MR, Fn, En);
        dim3 gb(En / 64, MR / 64);
        gemm64<false, true><<<gb, 256>>>(hh, W2, b2, x, z, MR, En, Fn);
    }
    {   // norm2 -> out
        dim3 g(En / 8, Bn);
        inorm_kernel<<<g, 256>>>(z, g2, be2, out);
    }
}

// round 8
// speedup vs baseline: 2.6574x; 1.0211x over previous
#include <cuda_runtime.h>
#include <math.h>

#define Bn 4
#define Rn 512
#define Cn 512
#define En 256
#define Hn 16
#define Dn 16
#define Mn 16
#define Fn 512

// ---------------- packed f32x2 helpers ----------------
typedef unsigned long long u64;
struct __align__(16) U2 { u64 a, b; };

__device__ __forceinline__ u64 pk(float lo, float hi) {
    u64 r; asm("mov.b64 %0,{%1,%2};" : "=l"(r) : "f"(lo), "f"(hi)); return r;
}
__device__ __forceinline__ void upk(u64 v, float& lo, float& hi) {
    asm("mov.b64 {%0,%1},%2;" : "=f"(lo), "=f"(hi) : "l"(v));
}
__device__ __forceinline__ u64 fma2(u64 a, u64 b, u64 c) {
    u64 d; asm("fma.rn.f32x2 %0,%1,%2,%3;" : "=l"(d) : "l"(a), "l"(b), "l"(c)); return d;
}
__device__ __forceinline__ u64 add2(u64 a, u64 b) {
    u64 d; asm("add.rn.f32x2 %0,%1,%2;" : "=l"(d) : "l"(a), "l"(b)); return d;
}
__device__ __forceinline__ u64 abs2(u64 x) { return x & 0x7FFFFFFF7FFFFFFFULL; }
__device__ __forceinline__ u64 shflx2(u64 v, int m) {
    float lo, hi; upk(v, lo, hi);
    lo = __shfl_xor_sync(0xFFFFFFFFu, lo, m);
    hi = __shfl_xor_sync(0xFFFFFFFFu, hi, m);
    return pk(lo, hi);
}

// ---------------- scratch ----------------
__device__ float g_q[Bn*Rn*En];
__device__ float g_k[Bn*Cn*En];
__device__ float g_v[Bn*Cn*En];
__device__ float g_att[Bn*Rn*En];
__device__ float g_y[Bn*Rn*En];
__device__ float g_x[Bn*Rn*En];
__device__ float g_h[Bn*Rn*Fn];
__device__ float g_z[Bn*Rn*En];

// ---------------- SGEMM: BM=BN=64, BK=16, 256 thr, double-buffered ----------------
template<bool RELU, bool RES>
__device__ __forceinline__
void gemm_body(const float* __restrict__ A, const float* __restrict__ B,
               const float* __restrict__ bias, const float* __restrict__ res,
               float* __restrict__ C, int M, int N, int K)
{
    __shared__ float As[2][16][64];
    __shared__ float Bs[2][16][64];
    const int tid = threadIdx.x;
    const int tx = tid & 15;
    const int ty = tid >> 4;
    const int m0 = blockIdx.y * 64;
    const int n0 = blockIdx.x * 64;

    const int arow = tid >> 2;
    const int acol = (tid & 3) * 4;
    const int brow = tid >> 4;
    const int bcol = (tid & 15) * 4;

    const float* Aptr = &A[(size_t)(m0 + arow) * K + acol];
    const float* Bptr = &B[(size_t)brow * N + n0 + bcol];

    u64 acc2[4][2] = {};

    {
        float4 av = *reinterpret_cast<const float4*>(Aptr);
        float4 bv = *reinterpret_cast<const float4*>(Bptr);
        As[0][acol + 0][arow] = av.x;
        As[0][acol + 1][arow] = av.y;
        As[0][acol + 2][arow] = av.z;
        As[0][acol + 3][arow] = av.w;
        *reinterpret_cast<float4*>(&Bs[0][brow][bcol]) = bv;
    }
    __syncthreads();

    int buf = 0;
    for (int k0 = 0; k0 < K; k0 += 16) {
        float4 nav, nbv;
        const bool more = (k0 + 16) < K;
        if (more) {
            nav = *reinterpret_cast<const float4*>(Aptr + (k0 + 16));
            nbv = *reinterpret_cast<const float4*>(Bptr + (size_t)(k0 + 16) * N);
        }
#pragma unroll
        for (int k = 0; k < 16; k++) {
            float4 a4 = *reinterpret_cast<const float4*>(&As[buf][k][ty * 4]);
            float4 b4 = *reinterpret_cast<const float4*>(&Bs[buf][k][tx * 4]);
            u64 b01 = pk(b4.x, b4.y);
            u64 b23 = pk(b4.z, b4.w);
            u64 a0 = pk(a4.x, a4.x), a1 = pk(a4.y, a4.y);
            u64 a2 = pk(a4.z, a4.z), a3 = pk(a4.w, a4.w);
            acc2[0][0] = fma2(a0, b01, acc2[0][0]); acc2[0][1] = fma2(a0, b23, acc2[0][1]);
            acc2[1][0] = fma2(a1, b01, acc2[1][0]); acc2[1][1] = fma2(a1, b23, acc2[1][1]);
            acc2[2][0] = fma2(a2, b01, acc2[2][0]); acc2[2][1] = fma2(a2, b23, acc2[2][1]);
            acc2[3][0] = fma2(a3, b01, acc2[3][0]); acc2[3][1] = fma2(a3, b23, acc2[3][1]);
        }
        if (more) {
            __syncthreads();
            int nb = buf ^ 1;
            As[nb][acol + 0][arow] = nav.x;
            As[nb][acol + 1][arow] = nav.y;
            As[nb][acol + 2][arow] = nav.z;
            As[nb][acol + 3][arow] = nav.w;
            *reinterpret_cast<float4*>(&Bs[nb][brow][bcol]) = nbv;
            __syncthreads();
            buf = nb;
        }
    }

#pragma unroll
    for (int i = 0; i < 4; i++) {
        int m = m0 + ty * 4 + i;
        float c0, c1, c2, c3;
        upk(acc2[i][0], c0, c1);
        upk(acc2[i][1], c2, c3);
        float vals[4] = {c0, c1, c2, c3};
#pragma unroll
        for (int j = 0; j < 4; j++) {
            int n = n0 + tx * 4 + j;
            float v = vals[j];
            if (bias) v += bias[n];
            if (RES)  v += res[(size_t)m * N + n];
            if (RELU) v = fmaxf(v, 0.0f);
            C[(size_t)m * N + n] = v;
        }
    }
}

template<bool RELU, bool RES>
__global__ __launch_bounds__(256, 3)
void gemm64(const float* __restrict__ A, const float* __restrict__ B,
            const float* __restrict__ bias, const float* __restrict__ res,
            float* __restrict__ C, int M, int N, int K)
{
    gemm_body<RELU, RES>(A, B, bias, res, C, M, N, K);
}

__global__ __launch_bounds__(256, 3)
void qkv_gemm(const float* __restrict__ row_emb, const float* __restrict__ col_emb,
              const float* __restrict__ Wq, const float* __restrict__ Wk,
              const float* __restrict__ Wv,
              float* __restrict__ q, float* __restrict__ k, float* __restrict__ v)
{
    const float* A; const float* B; float* C;
    if (blockIdx.z == 0)      { A = row_emb; B = Wq; C = q; }
    else if (blockIdx.z == 1) { A = col_emb; B = Wk; C = k; }
    else                      { A = col_emb; B = Wv; C = v; }
    gemm_body<false, false>(A, B, nullptr, nullptr, C, Bn * Rn, En, En);
}

// ---------------- fused attention ----------------
// grid (B*H, R/32), 256 thr (8 warps). Each warp handles 2 sequential groups
// of row pairs packed into f32x2 lanes. Mix MLP split into precomputed linear
// part (A·dot + B·cost + C) plus Σ_m w2h·|t_m|.
#define KV_STRIDE 20
#define ROWS_PER_BLK 32
#define ATTN_SMEM ((Cn * KV_STRIDE * 2 + ROWS_PER_BLK * Dn) * (int)sizeof(float))

__global__ __launch_bounds__(256, 2)
void attn_kernel(const float* __restrict__ Q, const float* __restrict__ K,
                 const float* __restrict__ V, const float* __restrict__ cost,
                 const float* __restrict__ mix1_w, const float* __restrict__ mix1_b,
                 const float* __restrict__ mix2_w, const float* __restrict__ mix2_b,
                 float* __restrict__ Out)
{
    extern __shared__ float sh[];
    float* ksh = sh;                        // 512 x 20
    float* vsh = sh + Cn * KV_STRIDE;       // 512 x 20
    float* qsh = vsh + Cn * KV_STRIDE;      // 32 x 16

    __shared__ U2 swA[Mn];    // {wd2, wc2}
    __shared__ U2 swB[Mn];    // {wb2, w2h2}
    __shared__ u64 sA2, sB2, sC2;   // linear-part coefficients (packed)

    const int tid = threadIdx.x;
    const int b = blockIdx.x >> 4;
    const int h = blockIdx.x & 15;
    const int r0 = blockIdx.y * ROWS_PER_BLK;

    if (tid < Mn) {
        float wd = mix1_w[h * 2 * Mn + tid];
        float wc = mix1_w[h * 2 * Mn + Mn + tid];
        float wb = mix1_b[h * Mn + tid];
        float w2h = 0.5f * mix2_w[h * Mn + tid];
        swA[tid].a = pk(wd, wd);
        swA[tid].b = pk(wc, wc);
        swB[tid].a = pk(wb, wb);
        swB[tid].b = pk(w2h, w2h);
    }
    if (tid == 0) {
        float Af = 0.0f, Bf = 0.0f, Cf = mix2_b[h];
#pragma unroll
        for (int m = 0; m < Mn; m++) {
            float w2h = 0.5f * mix2_w[h * Mn + m];
            Af = fmaf(w2h, mix1_w[h * 2 * Mn + m], Af);
            Bf = fmaf(w2h, mix1_w[h * 2 * Mn + Mn + m], Bf);
            Cf = fmaf(w2h, mix1_b[h * Mn + m], Cf);
        }
        sA2 = pk(Af, Af);
        sB2 = pk(Bf, Bf);
        sC2 = pk(Cf, Cf);
    }

    for (int idx = tid; idx < Cn * 4; idx += 256) {
        int c = idx >> 2, g = idx & 3;
        size_t src = ((size_t)(b * Cn + c)) * En + h * Dn + g * 4;
        *reinterpret_cast<float4*>(&ksh[c * KV_STRIDE + g * 4]) =
            *reinterpret_cast<const float4*>(&K[src]);
        *reinterpret_cast<float4*>(&vsh[c * KV_STRIDE + g * 4]) =
            *reinterpret_cast<const float4*>(&V[src]);
    }
    for (int idx = tid; idx < ROWS_PER_BLK * Dn; idx += 256) {
        int rr = idx >> 4, d = idx & 15;
        qsh[idx] = Q[((size_t)(b * Rn + r0 + rr)) * En + h * Dn + d];
    }
    __syncthreads();

    const int warp = tid >> 5;
    const int lane = tid & 31;
    const u64 A2 = sA2, B2 = sB2, C2 = sC2;

#pragma unroll 1
    for (int grp = 0; grp < 2; grp++) {
        const int ra = r0 + grp * 16 + warp;
        const int rb = ra + 8;
        const int qoff = grp * 16 + warp;

        const float* crA = &cost[((size_t)(b * Rn + ra)) * Cn];
        const float* crB = &cost[((size_t)(b * Rn + rb)) * Cn];

        u64 mx2[16];

        // ---------------- phase 1: scores + mix MLP ----------------
#pragma unroll
        for (int st = 0; st < 2; st++) {
            u64 dot2[8], cv2[8];
            {
                const u64* pa = reinterpret_cast<const u64*>(&qsh[qoff * Dn]);
                const u64* pb = reinterpret_cast<const u64*>(&qsh[(qoff + 8) * Dn]);
                u64 qa[8], qb[8];
#pragma unroll
                for (int j = 0; j < 8; j++) { qa[j] = pa[j]; qb[j] = pb[j]; }
#pragma unroll
                for (int i = 0; i < 8; i++) {
                    int c = lane + 32 * (st * 8 + i);
                    const U2* kp = reinterpret_cast<const U2*>(&ksh[c * KV_STRIDE]);
                    U2 k01 = kp[0], k23 = kp[1], k45 = kp[2], k67 = kp[3];
                    u64 aA = 0, aB = 0;
                    aA = fma2(qa[0], k01.a, aA); aB = fma2(qb[0], k01.a, aB);
                    aA = fma2(qa[1], k01.b, aA); aB = fma2(qb[1], k01.b, aB);
                    aA = fma2(qa[2], k23.a, aA); aB = fma2(qb[2], k23.a, aB);
                    aA = fma2(qa[3], k23.b, aA); aB = fma2(qb[3], k23.b, aB);
                    aA = fma2(qa[4], k45.a, aA); aB = fma2(qb[4], k45.a, aB);
                    aA = fma2(qa[5], k45.b, aA); aB = fma2(qb[5], k45.b, aB);
                    aA = fma2(qa[6], k67.a, aA); aB = fma2(qb[6], k67.a, aB);
                    aA = fma2(qa[7], k67.b, aA); aB = fma2(qb[7], k67.b, aB);
                    float x0, x1, y0, y1;
                    upk(aA, x0, x1); upk(aB, y0, y1);
                    dot2[i] = pk((x0 + x1) * 0.25f, (y0 + y1) * 0.25f);
                    cv2[i]  = pk(__ldg(&crA[c]), __ldg(&crB[c]));
                }
            }
            // abs part: acc = Σ_m w2h·|wd·dot + wc·cost + wb|
            u64 acc[8] = {};
#pragma unroll
            for (int m = 0; m < Mn; m++) {
                U2 w1 = swA[m];
                U2 w2 = swB[m];
#pragma unroll
                for (int i = 0; i < 8; i++) {
                    u64 t = fma2(dot2[i], w1.a, fma2(cv2[i], w1.b, w2.a));
                    acc[i] = fma2(abs2(t), w2.b, acc[i]);
                }
            }
            // linear part folded in: mixed = A·dot + B·cost + (C + acc)
#pragma unroll
            for (int i = 0; i < 8; i++) {
                mx2[st * 8 + i] = fma2(dot2[i], A2, fma2(cv2[i], B2, add2(C2, acc[i])));
            }
        }

        // ---------------- phase 2: softmax + PV ----------------
        float Ma = -1e30f, Mb = -1e30f;
#pragma unroll
        for (int i = 0; i < 16; i++) {
            float xa, xb; upk(mx2[i], xa, xb);
            Ma = fmaxf(Ma, xa); Mb = fmaxf(Mb, xb);
        }
#pragma unroll
        for (int off = 16; off; off >>= 1) {
            Ma = fmaxf(Ma, __shfl_xor_sync(0xFFFFFFFFu, Ma, off));
            Mb = fmaxf(Mb, __shfl_xor_sync(0xFFFFFFFFu, Mb, off));
        }

        u64 oa[8] = {}, ob[8] = {};
        float ssa = 0.0f, ssb = 0.0f;
#pragma unroll
        for (int i = 0; i < 16; i++) {
            int c = lane + 32 * i;
            float xa, xb; upk(mx2[i], xa, xb);
            float ea = __expf(xa - Ma);
            float eb = __expf(xb - Mb);
            ssa += ea; ssb += eb;
            const U2* vp = reinterpret_cast<const U2*>(&vsh[c * KV_STRIDE]);
            U2 v01 = vp[0], v23 = vp[1], v45 = vp[2], v67 = vp[3];
            u64 ea2 = pk(ea, ea), eb2 = pk(eb, eb);
            oa[0] = fma2(ea2, v01.a, oa[0]); ob[0] = fma2(eb2, v01.a, ob[0]);
            oa[1] = fma2(ea2, v01.b, oa[1]); ob[1] = fma2(eb2, v01.b, ob[1]);
            oa[2] = fma2(ea2, v23.a, oa[2]); ob[2] = fma2(eb2, v23.a, ob[2]);
            oa[3] = fma2(ea2, v23.b, oa[3]); ob[3] = fma2(eb2, v23.b, ob[3]);
            oa[4] = fma2(ea2, v45.a, oa[4]); ob[4] = fma2(eb2, v45.a, ob[4]);
            oa[5] = fma2(ea2, v45.b, oa[5]); ob[5] = fma2(eb2, v45.b, ob[5]);
            oa[6] = fma2(ea2, v67.a, oa[6]); ob[6] = fma2(eb2, v67.a, ob[6]);
            oa[7] = fma2(ea2, v67.b, oa[7]); ob[7] = fma2(eb2, v67.b, ob[7]);
        }

#pragma unroll
        for (int off = 16; off; off >>= 1) {
            ssa += __shfl_xor_sync(0xFFFFFFFFu, ssa, off);
            ssb += __shfl_xor_sync(0xFFFFFFFFu, ssb, off);
        }
        const float inva = 1.0f / ssa;
        const float invb = 1.0f / ssb;

        // ---- recursive-halving reduction: lane -> (row = lane>=16, d = lane&15) ----
        const bool hi16 = (lane & 16) != 0;
        u64 k8[8];
#pragma unroll
        for (int j = 0; j < 8; j++) {
            u64 kp_ = hi16 ? ob[j] : oa[j];
            u64 sd  = hi16 ? oa[j] : ob[j];
            k8[j] = add2(kp_, shflx2(sd, 16));
        }
        const bool hb8 = (lane & 8) != 0;
        u64 k4[4];
#pragma unroll
        for (int j = 0; j < 4; j++) {
            u64 kp_ = hb8 ? k8[j + 4] : k8[j];
            u64 sd  = hb8 ? k8[j] : k8[j + 4];
            k4[j] = add2(kp_, shflx2(sd, 8));
        }
        const bool hb4 = (lane & 4) != 0;
        u64 k2[2];
#pragma unroll
        for (int j = 0; j < 2; j++) {
            u64 kp_ = hb4 ? k4[j + 2] : k4[j];
            u64 sd  = hb4 ? k4[j] : k4[j + 2];
            k2[j] = add2(kp_, shflx2(sd, 4));
        }
        const bool hb2 = (lane & 2) != 0;
        u64 k1 = add2(hb2 ? k2[1] : k2[0], shflx2(hb2 ? k2[0] : k2[1], 2));
        float lo, hi; upk(k1, lo, hi);
        float kf = (lane & 1) ? hi : lo;
        float sf = (lane & 1) ? lo : hi;
        float val = kf + __shfl_xor_sync(0xFFFFFFFFu, sf, 1);

        const float invv = hi16 ? invb : inva;
        const int  rw   = hi16 ? rb : ra;
        Out[((size_t)(b * Rn + rw)) * En + h * Dn + (lane & 15)] = val * invv;
    }
}

// ---------------- instance norm: grid (E/4, B), 256 thr, 1 float4 col/block ----------------
__global__ __launch_bounds__(256)
void inorm_kernel(const float* __restrict__ X, const float* __restrict__ gamma,
                  const float* __restrict__ beta, float* __restrict__ Y)
{
    const int b = blockIdx.y;
    const int e4 = blockIdx.x;              // 0..63
    const int tid = threadIdx.x;
    const int lane = tid & 31;
    const int warp = tid >> 5;
    const float4* xb = reinterpret_cast<const float4*>(X + (size_t)b * Rn * En);
    float4* yb = reinterpret_cast<float4*>(Y + (size_t)b * Rn * En);
    const int s4 = En / 4;                  // 64

    float4 v0 = xb[(size_t)tid * s4 + e4];
    float4 v1 = xb[(size_t)(tid + 256) * s4 + e4];
    float4 s, s2;
    s.x = v0.x + v1.x; s.y = v0.y + v1.y; s.z = v0.z + v1.z; s.w = v0.w + v1.w;
    s2.x = v0.x*v0.x + v1.x*v1.x; s2.y = v0.y*v0.y + v1.y*v1.y;
    s2.z = v0.z*v0.z + v1.z*v1.z; s2.w = v0.w*v0.w + v1.w*v1.w;

#pragma unroll
    for (int off = 16; off; off >>= 1) {
        s.x += __shfl_xor_sync(0xFFFFFFFFu, s.x, off);
        s.y += __shfl_xor_sync(0xFFFFFFFFu, s.y, off);
        s.z += __shfl_xor_sync(0xFFFFFFFFu, s.z, off);
        s.w += __shfl_xor_sync(0xFFFFFFFFu, s.w, off);
        s2.x += __shfl_xor_sync(0xFFFFFFFFu, s2.x, off);
        s2.y += __shfl_xor_sync(0xFFFFFFFFu, s2.y, off);
        s2.z += __shfl_xor_sync(0xFFFFFFFFu, s2.z, off);
        s2.w += __shfl_xor_sync(0xFFFFFFFFu, s2.w, off);
    }
    __shared__ float4 ws[8], ws2[8];
    __shared__ float4 sa4, sc4;
    if (lane == 0) { ws[warp] = s; ws2[warp] = s2; }
    __syncthreads();
    if (tid == 0) {
        float4 t = ws[0], t2 = ws2[0];
#pragma unroll
        for (int j = 1; j < 8; j++) {
            t.x += ws[j].x; t.y += ws[j].y; t.z += ws[j].z; t.w += ws[j].w;
            t2.x += ws2[j].x; t2.y += ws2[j].y; t2.z += ws2[j].z; t2.w += ws2[j].w;
        }
        float4 gm = reinterpret_cast<const float4*>(gamma)[e4];
        float4 bt = reinterpret_cast<const float4*>(beta)[e4];
        float4 a, c;
        float mean, var, rs;
        mean = t.x * (1.0f / Rn); var = t2.x * (1.0f / Rn) - mean * mean;
        rs = rsqrtf(var + 1e-5f); a.x = gm.x * rs; c.x = bt.x - mean * a.x;
        mean = t.y * (1.0f / Rn); var = t2.y * (1.0f / Rn) - mean * mean;
        rs = rsqrtf(var + 1e-5f); a.y = gm.y * rs; c.y = bt.y - mean * a.y;
        mean = t.z * (1.0f / Rn); var = t2.z * (1.0f / Rn) - mean * mean;
        rs = rsqrtf(var + 1e-5f); a.z = gm.z * rs; c.z = bt.z - mean * a.z;
        mean = t.w * (1.0f / Rn); var = t2.w * (1.0f / Rn) - mean * mean;
        rs = rsqrtf(var + 1e-5f); a.w = gm.w * rs; c.w = bt.w - mean * a.w;
        sa4 = a; sc4 = c;
    }
    __syncthreads();
    const float4 a = sa4, c = sc4;
    float4 o0, o1;
    o0.x = fmaf(v0.x, a.x, c.x); o0.y = fmaf(v0.y, a.y, c.y);
    o0.z = fmaf(v0.z, a.z, c.z); o0.w = fmaf(v0.w, a.w, c.w);
    o1.x = fmaf(v1.x, a.x, c.x); o1.y = fmaf(v1.y, a.y, c.y);
    o1.z = fmaf(v1.z, a.z, c.z); o1.w = fmaf(v1.w, a.w, c.w);
    yb[(size_t)tid * s4 + e4] = o0;
    yb[(size_t)(tid + 256) * s4 + e4] = o1;
}

// ---------------- launch ----------------
extern "C" void kernel_launch(void* const* d_in, const int* in_sizes, int n_in,
                              void* d_out, int out_size)
{
    const float* row_emb = (const float*)d_in[0];
    const float* col_emb = (const float*)d_in[1];
    const float* cost    = (const float*)d_in[2];
    const float* Wq      = (const float*)d_in[3];
    const float* Wk      = (const float*)d_in[4];
    const float* Wv      = (const float*)d_in[5];
    const float* mix1_w  = (const float*)d_in[6];
    const float* mix1_b  = (const float*)d_in[7];
    const float* mix2_w  = (const float*)d_in[8];
    const float* mix2_b  = (const float*)d_in[9];
    const float* Wc      = (const float*)d_in[10];
    const float* bc      = (const float*)d_in[11];
    const float* W1      = (const float*)d_in[12];
    const float* b1      = (const float*)d_in[13];
    const float* W2      = (const float*)d_in[14];
    const float* b2      = (const float*)d_in[15];
    const float* g1      = (const float*)d_in[16];
    const float* be1     = (const float*)d_in[17];
    const float* g2      = (const float*)d_in[18];
    const float* be2     = (const float*)d_in[19];
    float* out = (float*)d_out;

    float *q, *k, *v, *att, *y, *x, *hh, *z;
    cudaGetSymbolAddress((void**)&q,   g_q);
    cudaGetSymbolAddress((void**)&k,   g_k);
    cudaGetSymbolAddress((void**)&v,   g_v);
    cudaGetSymbolAddress((void**)&att, g_att);
    cudaGetSymbolAddress((void**)&y,   g_y);
    cudaGetSymbolAddress((void**)&x,   g_x);
    cudaGetSymbolAddress((void**)&hh,  g_h);
    cudaGetSymbolAddress((void**)&z,   g_z);

    cudaFuncSetAttribute(attn_kernel, cudaFuncAttributeMaxDynamicSharedMemorySize, ATTN_SMEM);

    const int MR = Bn * Rn;   // 2048

    {   // fused QKV
        dim3 g(En / 64, MR / 64, 3);
        qkv_gemm<<<g, 256>>>(row_emb, col_emb, Wq, Wk, Wv, q, k, v);
    }
    {   // fused attention
        dim3 g(Bn * Hn, Rn / ROWS_PER_BLK);
        attn_kernel<<<g, 256, ATTN_SMEM>>>(q, k, v, cost, mix1_w, mix1_b, mix2_w, mix2_b, att);
    }
    {   // combine + residual
        dim3 g(En / 64, MR / 64);
        gemm64<false, true><<<g, 256>>>(att, Wc, bc, row_emb, y, MR, En, En);
    }
    {   // norm1
        dim3 g(En / 4, Bn);
        inorm_kernel<<<g, 256>>>(y, g1, be1, x);
    }
    {   // FFN
        dim3 ga(Fn / 64, MR / 64);
        gemm64<true, false><<<ga, 256>>>(x, W1, b1, nullptr, hh, MR, Fn, En);
        dim3 gb(En / 64, MR / 64);
        gemm64<false, true><<<gb, 256>>>(hh, W2, b2, x, z, MR, En, Fn);
    }
    {   // norm2 -> out
        dim3 g(En / 4, Bn);
        inorm_kernel<<<g, 256>>>(z, g2, be2, out);
    }
}